// round 15
// baseline (speedup 1.0000x reference)
#include <cuda_runtime.h>
#include <cuda_fp16.h>
#include <math.h>
#include <stdint.h>

// ---------------------------------------------------------------- constants
#define S_LEN 2048
#define H_DIM 2048
#define NHEAD 16
#define DQK   128
#define DV    64
#define KVR   256
#define NEXP  8
#define INTER 1408
#define NFC1  (NEXP*INTER)   // 11264
#define CKV_P 512

#define KB_H    (H_DIM/64)      // 32
#define KB_KVR  (KVR/64)        // 4
#define KB_CTX  ((NHEAD*DV)/64) // 16
#define KB_FC2  (NFC1/64)       // 176

// ---------------------------------------------------------------- scratch (fp32)
__device__ float g_sa  [S_LEN*H_DIM];
__device__ float g_q   [S_LEN*H_DIM];
__device__ float g_ckv [S_LEN*CKV_P];
__device__ float g_kvn [S_LEN*KVR];
__device__ float g_kv  [S_LEN*H_DIM];
__device__ float g_x2  [S_LEN*H_DIM];
__device__ float g_mlp [S_LEN*H_DIM];
__device__ float g_pr  [S_LEN*NEXP];

// ---------------------------------------------------------------- scratch (blocked fp16)
__device__ __half g_sa_f [S_LEN*H_DIM];
__device__ __half g_kvn_f[S_LEN*KVR];
__device__ __half g_mlp_f[S_LEN*H_DIM];
__device__ __half g_ctx_f[S_LEN*NHEAD*DV];
__device__ __half g_hb_f [(size_t)S_LEN*NFC1];
__device__ __half g_qw_f [H_DIM*H_DIM];
__device__ __half g_kva_f[CKV_P*H_DIM];
__device__ __half g_kbw_f[H_DIM*KVR];
__device__ __half g_ow_f [H_DIM*NHEAD*DV];
__device__ __half g_f1_f [(size_t)NFC1*H_DIM];
__device__ __half g_f2_f [(size_t)H_DIM*NFC1];
__device__ __half g_qb_f [S_LEN*H_DIM];
__device__ __half g_kb_f [S_LEN*H_DIM];
__device__ __half g_vt_f [S_LEN*NHEAD*DV];

// ---------------------------------------------------------------- helpers
__device__ __forceinline__ uint32_t smem_u32(const void* p) {
    uint32_t a;
    asm("{ .reg .u64 t; cvta.to.shared.u64 t, %1; cvt.u32.u64 %0, t; }" : "=r"(a) : "l"(p));
    return a;
}
#define SWZ(off) ((off) ^ (((off) >> 3) & 0x70u))

__device__ __forceinline__ void ldsm_x4(uint32_t* r, uint32_t addr) {
    asm volatile("ldmatrix.sync.aligned.m8n8.x4.shared.b16 {%0,%1,%2,%3}, [%4];"
                 : "=r"(r[0]), "=r"(r[1]), "=r"(r[2]), "=r"(r[3]) : "r"(addr));
}
__device__ __forceinline__ void mma_fp16(float* c, const uint32_t* a, const uint32_t* b) {
    asm volatile("mma.sync.aligned.m16n8k16.row.col.f32.f16.f16.f32 "
                 "{%0,%1,%2,%3}, {%4,%5,%6,%7}, {%8,%9}, {%0,%1,%2,%3};"
                 : "+f"(c[0]), "+f"(c[1]), "+f"(c[2]), "+f"(c[3])
                 : "r"(a[0]), "r"(a[1]), "r"(a[2]), "r"(a[3]), "r"(b[0]), "r"(b[1]));
}
#define MBAR_INIT(a, c) asm volatile("mbarrier.init.shared.b64 [%0], %1;" :: "r"(a), "r"(c) : "memory")
#define MBAR_EXPECT(a, b) asm volatile("mbarrier.arrive.expect_tx.shared.b64 _, [%0], %1;" :: "r"(a), "r"(b) : "memory")
#define MBAR_WAIT(a, ph) do { \
    asm volatile("{\n\t.reg .pred P1;\n\tWL_%=:\n\t" \
        "mbarrier.try_wait.parity.acquire.cta.shared::cta.b64 P1, [%0], %1, 0x989680;\n\t" \
        "@P1 bra.uni WD_%=;\n\tbra.uni WL_%=;\n\tWD_%=:\n\t}" \
        :: "r"(a), "r"(ph) : "memory"); } while (0)
__device__ __forceinline__ void bulk_g2s(uint32_t dst, const void* src, uint32_t bytes, uint32_t mbar) {
    asm volatile("cp.async.bulk.shared::cluster.global.mbarrier::complete_tx::bytes [%0], [%1], %2, [%3];"
                 :: "r"(dst), "l"(src), "r"(bytes), "r"(mbar) : "memory");
}

__device__ __forceinline__ uint32_t pack2(float x, float y) {
    __half2 h = __floats2half2_rn(x, y);
    return *reinterpret_cast<uint32_t*>(&h);
}
__device__ __forceinline__ void cvt8(const float* v, uint4& p) {
    p = make_uint4(pack2(v[0], v[1]), pack2(v[2], v[3]), pack2(v[4], v[5]), pack2(v[6], v[7]));
}
__device__ __forceinline__ size_t blk_chunk_off(int blk_idx, int row, int c8) {
    uint32_t inner = (uint32_t)row * 128u + (uint32_t)c8 * 16u;
    return ((size_t)blk_idx << 14) + SWZ(inner);
}

// ---------------------------------------------------------------- weight converts
__global__ void cvt_blk_kernel(const float* __restrict__ src, __half* __restrict__ D,
                               int Npad, int Nreal, int K) {
    const int KC = K >> 3;
    const int KBk = K >> 6;
    const size_t tot = (size_t)Npad * KC;
    for (size_t idx = (size_t)blockIdx.x * blockDim.x + threadIdx.x; idx < tot;
         idx += (size_t)gridDim.x * blockDim.x) {
        int n = (int)(idx / KC), c = (int)(idx - (size_t)n * KC);
        float v[8];
        if (n < Nreal) {
            const float4 f0 = *(const float4*)(src + (size_t)n * K + c * 8);
            const float4 f1 = *(const float4*)(src + (size_t)n * K + c * 8 + 4);
            v[0]=f0.x; v[1]=f0.y; v[2]=f0.z; v[3]=f0.w; v[4]=f1.x; v[5]=f1.y; v[6]=f1.z; v[7]=f1.w;
        } else {
            #pragma unroll
            for (int j = 0; j < 8; j++) v[j] = 0.f;
        }
        uint4 p; cvt8(v, p);
        *(uint4*)((char*)D + blk_chunk_off((n >> 7) * KBk + (c >> 3), n & 127, c & 7)) = p;
    }
}

__global__ void cvt_fc2_blk_kernel(const float* __restrict__ w, __half* __restrict__ D) {
    const int KC = NFC1 >> 3;
    const size_t tot = (size_t)H_DIM * KC;
    for (size_t idx = (size_t)blockIdx.x * blockDim.x + threadIdx.x; idx < tot;
         idx += (size_t)gridDim.x * blockDim.x) {
        int n = (int)(idx / KC), c = (int)(idx - (size_t)n * KC);
        int k0 = c * 8;
        int e = k0 / INTER, i = k0 - e * INTER;
        const float* sp = w + ((size_t)e * H_DIM + n) * INTER + i;
        float v[8];
        const float4 f0 = *(const float4*)sp;
        const float4 f1 = *(const float4*)(sp + 4);
        v[0]=f0.x; v[1]=f0.y; v[2]=f0.z; v[3]=f0.w; v[4]=f1.x; v[5]=f1.y; v[6]=f1.z; v[7]=f1.w;
        uint4 p; cvt8(v, p);
        *(uint4*)((char*)D + blk_chunk_off((n >> 7) * KB_FC2 + (c >> 3), n & 127, c & 7)) = p;
    }
}

// ---------------------------------------------------------------- rmsnorm (+blocked fp16)
__global__ void rmsnorm_kernel(const float* __restrict__ x, const float* __restrict__ w,
                               float* __restrict__ y, __half* __restrict__ yf,
                               int W, int xs, int KBk)
{
    int s = blockIdx.x, tid = threadIdx.x;
    const float* xr = x + (size_t)s * xs;
    float ss = 0.f;
    for (int i = tid; i < W; i += 256) { float v = xr[i]; ss += v * v; }
    __shared__ float red[256];
    red[tid] = ss; __syncthreads();
    for (int o = 128; o > 0; o >>= 1) { if (tid < o) red[tid] += red[tid + o]; __syncthreads(); }
    float inv = rsqrtf(red[0] / (float)W + 1e-6f);
    float* yr = y + (size_t)s * W;
    const int KC = W >> 3;
    for (int c = tid; c < KC; c += 256) {
        float v[8];
        #pragma unroll
        for (int j = 0; j < 8; j++) {
            int i = c * 8 + j;
            v[j] = w[i] * xr[i] * inv;
            yr[i] = v[j];
        }
        uint4 p; cvt8(v, p);
        *(uint4*)((char*)yf + blk_chunk_off((s >> 7) * KBk + (c >> 3), s & 127, c & 7)) = p;
    }
}

// ---------------------------------------------------------------- gate softmax
__global__ void gate_kernel(const float* __restrict__ x, const float* __restrict__ w,
                            float* __restrict__ probs)
{
    int s = blockIdx.x;
    int warp = threadIdx.x >> 5, lane = threadIdx.x & 31;
    const float* xr = x + (size_t)s * H_DIM;
    const float* wr = w + (size_t)warp * H_DIM;
    float acc = 0.f;
    for (int i = lane; i < H_DIM; i += 32) acc += xr[i] * wr[i];
    #pragma unroll
    for (int o = 16; o; o >>= 1) acc += __shfl_xor_sync(0xffffffffu, acc, o);
    __shared__ float lg[8];
    if (lane == 0) lg[warp] = acc;
    __syncthreads();
    if (threadIdx.x == 0) {
        float mx = lg[0];
        #pragma unroll
        for (int e = 1; e < 8; e++) mx = fmaxf(mx, lg[e]);
        float sum = 0.f, ev[8];
        #pragma unroll
        for (int e = 0; e < 8; e++) { ev[e] = __expf(lg[e] - mx); sum += ev[e]; }
        float invs = 1.f / sum;
        #pragma unroll
        for (int e = 0; e < 8; e++) probs[(size_t)s * 8 + e] = ev[e] * invs;
    }
}

// ---------------------------------------------------------------- fused rope + attention converts
__global__ void qk_cvt_kernel(const int* __restrict__ positions,
                              const float* __restrict__ q, const float* __restrict__ kv,
                              const float* __restrict__ ckv,
                              __half* __restrict__ Qf, __half* __restrict__ Kf)
{
    const int s = blockIdx.x, tid = threadIdx.x;
    const int h = tid >> 4, d = (tid & 15) * 8;
    const float p = (float)positions[s];
    const size_t off = ((size_t)((h * 16 + (s >> 7)) * 2 + (d >> 6)) << 14)
                       + SWZ((uint32_t)(s & 127) * 128u + (uint32_t)(d & 63) * 2u);
    float cs[8], sn[8];
    if (d >= 64) {
        #pragma unroll
        for (int j = 0; j < 8; j++) {
            int jj = (d - 64 + j) & 31;
            float ang = p * exp2f(-(float)jj * 0.41524101186092f);
            __sincosf(ang, &sn[j], &cs[j]);
        }
    }
    {
        const float* qr = q + (size_t)s * H_DIM + h * DQK;
        float v[8];
        #pragma unroll
        for (int j = 0; j < 8; j++) {
            int dd = d + j;
            if (dd < 64) v[j] = qr[dd];
            else if (dd < 96) v[j] = qr[dd] * cs[j] - qr[dd + 32] * sn[j];
            else             v[j] = qr[dd] * cs[j] + qr[dd - 32] * sn[j];
        }
        uint4 pk; cvt8(v, pk);
        *(uint4*)((char*)Qf + off) = pk;
    }
    {
        const float* kr = ckv + (size_t)s * CKV_P + 256 - 64;
        const float* nr = kv + (size_t)s * H_DIM + h * DQK;
        float v[8];
        #pragma unroll
        for (int j = 0; j < 8; j++) {
            int dd = d + j;
            if (dd < 64) v[j] = nr[dd];
            else if (dd < 96) v[j] = kr[dd] * cs[j] - kr[dd + 32] * sn[j];
            else             v[j] = kr[dd] * cs[j] + kr[dd - 32] * sn[j];
        }
        uint4 pk; cvt8(v, pk);
        *(uint4*)((char*)Kf + off) = pk;
    }
}

__global__ void vt_cvt_kernel(const float* __restrict__ kv, __half* __restrict__ Vf)
{
    __shared__ float vt[128][65];
    const int sb = blockIdx.x, h = blockIdx.y, tid = threadIdx.x;
    #pragma unroll
    for (int i = 0; i < 32; i++) {
        int idx = tid + i * 256;
        int r = idx >> 6, c = idx & 63;
        vt[r][c] = kv[(size_t)(sb * 128 + r) * H_DIM + h * DQK + 64 + c];
    }
    __syncthreads();
    #pragma unroll
    for (int i = 0; i < 4; i++) {
        int idx = tid + i * 256;
        int dd = idx >> 4, s0 = (idx & 15) * 8;
        float v[8];
        #pragma unroll
        for (int j = 0; j < 8; j++) v[j] = vt[s0 + j][dd];
        uint4 p; cvt8(v, p);
        size_t off = ((size_t)(h * 16 + sb) << 14) + (size_t)(s0 >> 6) * 8192u
                     + SWZ((uint32_t)dd * 128u + (uint32_t)(s0 & 63) * 2u);
        *(uint4*)((char*)Vf + off) = p;
    }
}

// ---------------------------------------------------------------- fp16 bulk-copy GEMM
#define BG_STAGE_B  32768u
#define BG_SMEM     (1024 + 3 * 32768)
#define OFF_A 0u
#define OFF_B 16384u

template<int EPI>
__global__ __launch_bounds__(256, 2) void bgemm(
    const __half* __restrict__ Ab, const __half* __restrict__ Bb,
    int N, int KBk,
    float* __restrict__ C, const float* __restrict__ extra,
    __half* __restrict__ Cf, int CKB,
    const __half* __restrict__ Bb2, float* __restrict__ C2, int nbSplit, int N2)
{
    extern __shared__ char smem[];
    const uint32_t sb = smem_u32(smem);
    const uint32_t tb = (sb + 1023u) & ~1023u;
    const int tid = threadIdx.x, wid = tid >> 5, lane = tid & 31;

    const __half* Buse = Bb;
    float* Cuse = C;
    int Nuse = N;
    int bx = blockIdx.x;
    if (Bb2 != nullptr && bx >= nbSplit) {
        Buse = Bb2; Cuse = C2; Nuse = N2; bx -= nbSplit;
    }
    const int n0 = bx * 128, m0 = blockIdx.y * 128;
    const int mb = blockIdx.y, nb = bx;
    const int wm = (wid >> 2) * 64;
    const int wn = (wid & 3) * 32;

    if (tid == 0) { MBAR_INIT(sb, 1); MBAR_INIT(sb + 8, 1); MBAR_INIT(sb + 16, 1); }
    __syncthreads();

    auto load_stage = [&](int t) {
        const int s = t % 3;
        const uint32_t mb_addr = sb + s * 8;
        const uint32_t st = tb + s * BG_STAGE_B;
        MBAR_EXPECT(mb_addr, BG_STAGE_B);
        bulk_g2s(st + OFF_A, (const char*)Ab   + (((size_t)mb * KBk + t) << 14), 16384u, mb_addr);
        bulk_g2s(st + OFF_B, (const char*)Buse + (((size_t)nb * KBk + t) << 14), 16384u, mb_addr);
    };

    if (tid == 0) {
        #pragma unroll
        for (int i = 0; i < 3; i++) if (i < KBk) load_stage(i);
    }

    float acc[4][4][4];
    #pragma unroll
    for (int i = 0; i < 4; i++)
        #pragma unroll
        for (int j = 0; j < 4; j++)
            #pragma unroll
            for (int k = 0; k < 4; k++) acc[i][j][k] = 0.f;

    const uint32_t a_row = lane & 15, a_chk = lane >> 4;
    const uint32_t b_row = ((lane >> 4) & 1) * 8 + (lane & 7);
    const uint32_t b_chk = (lane >> 3) & 1;

    for (int t = 0; t < KBk; t++) {
        const int s = t % 3;
        MBAR_WAIT(sb + s * 8, (t / 3) & 1);
        const uint32_t st = tb + s * BG_STAGE_B;

        #pragma unroll
        for (int ks = 0; ks < 4; ks++) {
            uint32_t a[4][4], b[4][2];
            #pragma unroll
            for (int mt = 0; mt < 4; mt++) {
                uint32_t off = SWZ((uint32_t)(wm + mt * 16 + a_row) * 128u + (ks * 2 + a_chk) * 16u);
                ldsm_x4(a[mt], st + OFF_A + off);
            }
            #pragma unroll
            for (int p = 0; p < 2; p++) {
                uint32_t off = SWZ((uint32_t)(wn + p * 16 + b_row) * 128u + (ks * 2 + b_chk) * 16u);
                uint32_t r[4];
                ldsm_x4(r, st + OFF_B + off);
                b[2*p][0]=r[0]; b[2*p][1]=r[1]; b[2*p+1][0]=r[2]; b[2*p+1][1]=r[3];
            }
            #pragma unroll
            for (int mt = 0; mt < 4; mt++)
                #pragma unroll
                for (int nt = 0; nt < 4; nt++)
                    mma_fp16(acc[mt][nt], a[mt], b[nt]);
        }
        __syncthreads();
        if (tid == 0 && t + 3 < KBk) load_stage(t + 3);
    }

    #pragma unroll
    for (int mt = 0; mt < 4; mt++) {
        #pragma unroll
        for (int half = 0; half < 2; half++) {
            const int row = m0 + wm + mt * 16 + half * 8 + (lane >> 2);
            #pragma unroll
            for (int nt = 0; nt < 4; nt++) {
                const int col = n0 + wn + nt * 8 + (lane & 3) * 2;
                float v0 = acc[mt][nt][half * 2 + 0];
                float v1 = acc[mt][nt][half * 2 + 1];
                if (EPI == 0) {
                    *(float2*)&Cuse[(size_t)row * Nuse + col] = make_float2(v0, v1);
                } else if (EPI == 2) {
                    const float2 e2 = *(const float2*)&extra[(size_t)row * Nuse + col];
                    *(float2*)&Cuse[(size_t)row * Nuse + col] = make_float2(v0 + e2.x, v1 + e2.y);
                } else {
                    float pf = extra[(size_t)row * NEXP + (col / INTER)];
                    float s0 = v0 / (1.f + __expf(-v0)) * pf;
                    float s1 = v1 / (1.f + __expf(-v1)) * pf;
                    uint32_t inner = (uint32_t)(row & 127) * 128u + (uint32_t)(col & 63) * 2u;
                    size_t off = (((size_t)(row >> 7) * CKB + (col >> 6)) << 14) + SWZ(inner);
                    *(uint32_t*)((char*)Cf + off) = pack2(s0, s1);
                }
            }
        }
    }
}

// ---------------------------------------------------------------- fp16 flash attention
// 64-row KV chunks -> sc[8][4]+o[8][4]=64 regs, smem 82KB -> 2 CTAs/SM, no spill.
#define AT_SMEM (1024 + 32768 + 2 * 16384 + 2 * 8192)   // ~83KB

__global__ __launch_bounds__(256, 2) void attn_tc(
    const __half* __restrict__ Qg, const __half* __restrict__ Kg,
    const __half* __restrict__ Vg, __half* __restrict__ Cf)
{
    extern __shared__ char smem[];
    const uint32_t sbb = smem_u32(smem);
    const uint32_t tb = (sbb + 1023u) & ~1023u;
    const uint32_t QS = tb;                 // 32KB (two 16KB d-blocks)
    const uint32_t KS0 = tb + 32768u;       // 2 stages x 16KB
    const uint32_t VS0 = tb + 65536u;       // 2 stages x 8KB

    const int tid = threadIdx.x, wid = tid >> 5, lane = tid & 31;
    const int idx = (int)gridDim.x - 1 - (int)blockIdx.x;   // heavy first
    const int qt = idx >> 4, h = idx & 15;
    const int wq = wid * 16;
    const int r = lane >> 2, c2 = (lane & 3) * 2;
    const int nchunks = 2 * (qt + 1);

    if (tid == 0) { MBAR_INIT(sbb, 1); MBAR_INIT(sbb + 8, 1); MBAR_INIT(sbb + 16, 1); }
    __syncthreads();

    auto load_chunk = [&](int c) {
        const int s = c & 1;
        const uint32_t mb = sbb + 8 + s * 8;
        MBAR_EXPECT(mb, 24576u);
        const size_t kbase = ((size_t)((h * 16 + (c >> 1)) * 2) << 14) + (size_t)(c & 1) * 8192u;
        bulk_g2s(KS0 + s * 16384u,         (const char*)Kg + kbase,           8192u, mb);
        bulk_g2s(KS0 + s * 16384u + 8192u, (const char*)Kg + kbase + 16384u,  8192u, mb);
        const size_t vbase = ((size_t)(h * 16 + (c >> 1)) << 14) + (size_t)(c & 1) * 8192u;
        bulk_g2s(VS0 + s * 8192u,          (const char*)Vg + vbase,           8192u, mb);
    };

    if (tid == 0) {
        MBAR_EXPECT(sbb, 32768u);
        bulk_g2s(QS, (const char*)Qg + ((size_t)(h * 16 + qt) << 15), 32768u, sbb);
        load_chunk(0);
        if (nchunks > 1) load_chunk(1);
    }

    float sc[8][4];
    float o[8][4];
    #pragma unroll
    for (int i = 0; i < 8; i++)
        #pragma unroll
        for (int j = 0; j < 4; j++) o[i][j] = 0.f;
    float m0 = -1e30f, m1 = -1e30f, l0 = 0.f, l1 = 0.f;
    const float SCL = 0.08838834764831845f * 1.44269504088896f;

    const uint32_t a_row = lane & 15, a_chk = lane >> 4;
    const uint32_t b_row = ((lane >> 4) & 1) * 8 + (lane & 7);
    const uint32_t b_chk = (lane >> 3) & 1;

    for (int c = 0; c < nchunks; c++) {
        const int s = c & 1;
        MBAR_WAIT(sbb + 8 + s * 8, (c >> 1) & 1);
        if (c == 0) MBAR_WAIT(sbb, 0);
        const uint32_t KS = KS0 + s * 16384u;
        const uint32_t VS = VS0 + s * 8192u;

        // ---- S = Q K^T over 64 k rows
        #pragma unroll
        for (int nt = 0; nt < 8; nt++)
            #pragma unroll
            for (int j = 0; j < 4; j++) sc[nt][j] = 0.f;

        #pragma unroll
        for (int kc = 0; kc < 8; kc++) {
            const uint32_t qdb = (kc >> 2) * 16384u;       // Q d-block
            const uint32_t acol = ((uint32_t)(kc * 16) + a_chk * 8u) & 63u;
            uint32_t a[4];
            ldsm_x4(a, QS + qdb + SWZ((uint32_t)(wq + a_row) * 128u + acol * 2u));
            const uint32_t kdb = (kc >> 2) * 8192u;        // K d-sub-block in stage
            const uint32_t bcol = ((uint32_t)(kc * 16) + b_chk * 8u) & 63u;
            #pragma unroll
            for (int p = 0; p < 4; p++) {
                uint32_t rr[4];
                ldsm_x4(rr, KS + kdb + SWZ((uint32_t)(p * 16 + b_row) * 128u + bcol * 2u));
                uint32_t b0[2] = {rr[0], rr[1]}, b1[2] = {rr[2], rr[3]};
                mma_fp16(sc[2*p],   a, b0);
                mma_fp16(sc[2*p+1], a, b1);
            }
        }

        // ---- online softmax
        const bool diag = (c >= 2 * qt);
        float nm0 = m0, nm1 = m1;
        #pragma unroll
        for (int nt = 0; nt < 8; nt++) {
            #pragma unroll
            for (int j = 0; j < 4; j++) {
                float v = sc[nt][j] * SCL;
                if (diag) {
                    int col = c * 64 + nt * 8 + c2 + (j & 1);
                    int rowg = qt * 128 + wq + r + (j >> 1) * 8;
                    if (col > rowg) v = -1e30f;
                }
                sc[nt][j] = v;
            }
            nm0 = fmaxf(nm0, fmaxf(sc[nt][0], sc[nt][1]));
            nm1 = fmaxf(nm1, fmaxf(sc[nt][2], sc[nt][3]));
        }
        #pragma unroll
        for (int off = 1; off <= 2; off <<= 1) {
            nm0 = fmaxf(nm0, __shfl_xor_sync(0xffffffffu, nm0, off));
            nm1 = fmaxf(nm1, __shfl_xor_sync(0xffffffffu, nm1, off));
        }
        float rs0 = 0.f, rs1 = 0.f;
        #pragma unroll
        for (int nt = 0; nt < 8; nt++) {
            sc[nt][0] = exp2f(sc[nt][0] - nm0);
            sc[nt][1] = exp2f(sc[nt][1] - nm0);
            sc[nt][2] = exp2f(sc[nt][2] - nm1);
            sc[nt][3] = exp2f(sc[nt][3] - nm1);
            rs0 += sc[nt][0] + sc[nt][1];
            rs1 += sc[nt][2] + sc[nt][3];
        }
        #pragma unroll
        for (int off = 1; off <= 2; off <<= 1) {
            rs0 += __shfl_xor_sync(0xffffffffu, rs0, off);
            rs1 += __shfl_xor_sync(0xffffffffu, rs1, off);
        }
        float cr0 = exp2f(m0 - nm0), cr1 = exp2f(m1 - nm1);
        l0 = l0 * cr0 + rs0; l1 = l1 * cr1 + rs1;
        m0 = nm0; m1 = nm1;
        #pragma unroll
        for (int i = 0; i < 8; i++) {
            o[i][0] *= cr0; o[i][1] *= cr0;
            o[i][2] *= cr1; o[i][3] *= cr1;
        }

        // ---- O += P V over 64 k rows
        #pragma unroll
        for (int kc = 0; kc < 4; kc++) {
            uint32_t a[4];
            a[0] = pack2(sc[2*kc][0],   sc[2*kc][1]);
            a[1] = pack2(sc[2*kc][2],   sc[2*kc][3]);
            a[2] = pack2(sc[2*kc+1][0], sc[2*kc+1][1]);
            a[3] = pack2(sc[2*kc+1][2], sc[2*kc+1][3]);
            const uint32_t scol = (uint32_t)(kc * 16) + b_chk * 8u;
            #pragma unroll
            for (int p = 0; p < 4; p++) {
                uint32_t rr[4];
                ldsm_x4(rr, VS + SWZ((uint32_t)(p * 16 + b_row) * 128u + scol * 2u));
                uint32_t b0[2] = {rr[0], rr[1]}, b1[2] = {rr[2], rr[3]};
                mma_fp16(o[2*p],   a, b0);
                mma_fp16(o[2*p+1], a, b1);
            }
        }
        __syncthreads();
        if (tid == 0 && c + 2 < nchunks) load_chunk(c + 2);
    }

    const float i0 = 1.f / l0, i1 = 1.f / l1;
    #pragma unroll
    for (int nt = 0; nt < 8; nt++) {
        const int col = h * DV + nt * 8 + c2;
        #pragma unroll
        for (int half = 0; half < 2; half++) {
            const int row = qt * 128 + wq + r + half * 8;
            float inv = half ? i1 : i0;
            float v0 = o[nt][half * 2 + 0] * inv;
            float v1 = o[nt][half * 2 + 1] * inv;
            uint32_t inner = (uint32_t)(row & 127) * 128u + (uint32_t)(col & 63) * 2u;
            size_t off = (((size_t)(row >> 7) * KB_CTX + (col >> 6)) << 14) + SWZ(inner);
            *(uint32_t*)((char*)Cf + off) = pack2(v0, v1);
        }
    }
}

// ---------------------------------------------------------------- launch
extern "C" void kernel_launch(void* const* d_in, const int* in_sizes, int n_in,
                              void* d_out, int out_size)
{
    const int*   positions = (const int*)  d_in[0];
    const float* hidden    = (const float*)d_in[1];
    const float* in_ln     = (const float*)d_in[2];
    const float* qw        = (const float*)d_in[3];
    const float* kva_w     = (const float*)d_in[4];
    const float* kvaln     = (const float*)d_in[5];
    const float* kvb_w     = (const float*)d_in[6];
    const float* ow        = (const float*)d_in[7];
    const float* postln    = (const float*)d_in[8];
    const float* gatew     = (const float*)d_in[9];
    const float* fc1w      = (const float*)d_in[10];
    const float* fc2w      = (const float*)d_in[11];
    float* out = (float*)d_out;

    float *sa, *qb, *ckv, *kvn, *kvv, *x2, *mlp, *pr;
    cudaGetSymbolAddress((void**)&sa,  g_sa);
    cudaGetSymbolAddress((void**)&qb,  g_q);
    cudaGetSymbolAddress((void**)&ckv, g_ckv);
    cudaGetSymbolAddress((void**)&kvn, g_kvn);
    cudaGetSymbolAddress((void**)&kvv, g_kv);
    cudaGetSymbolAddress((void**)&x2,  g_x2);
    cudaGetSymbolAddress((void**)&mlp, g_mlp);
    cudaGetSymbolAddress((void**)&pr,  g_pr);

    __half *saf,*kvnf,*mlpf,*ctxf,*hbf,*qwf,*kvaf,*kbwf,*owf,*f1f,*f2f,*qbf,*kbf,*vtf;
    cudaGetSymbolAddress((void**)&saf,  g_sa_f);
    cudaGetSymbolAddress((void**)&kvnf, g_kvn_f);
    cudaGetSymbolAddress((void**)&mlpf, g_mlp_f);
    cudaGetSymbolAddress((void**)&ctxf, g_ctx_f);
    cudaGetSymbolAddress((void**)&hbf,  g_hb_f);
    cudaGetSymbolAddress((void**)&qwf,  g_qw_f);
    cudaGetSymbolAddress((void**)&kvaf, g_kva_f);
    cudaGetSymbolAddress((void**)&kbwf, g_kbw_f);
    cudaGetSymbolAddress((void**)&owf,  g_ow_f);
    cudaGetSymbolAddress((void**)&f1f,  g_f1_f);
    cudaGetSymbolAddress((void**)&f2f,  g_f2_f);
    cudaGetSymbolAddress((void**)&qbf,  g_qb_f);
    cudaGetSymbolAddress((void**)&kbf,  g_kb_f);
    cudaGetSymbolAddress((void**)&vtf,  g_vt_f);

    cudaFuncSetAttribute(bgemm<0>, cudaFuncAttributeMaxDynamicSharedMemorySize, BG_SMEM);
    cudaFuncSetAttribute(bgemm<1>, cudaFuncAttributeMaxDynamicSharedMemorySize, BG_SMEM);
    cudaFuncSetAttribute(bgemm<2>, cudaFuncAttributeMaxDynamicSharedMemorySize, BG_SMEM);
    cudaFuncSetAttribute(attn_tc,  cudaFuncAttributeMaxDynamicSharedMemorySize, AT_SMEM);

    static cudaStream_t s2 = nullptr;
    static cudaEvent_t evFork = nullptr, evQKA = nullptr, evKBW = nullptr,
                       evOW = nullptr, evF1 = nullptr, evF2 = nullptr;
    if (s2 == nullptr) {
        cudaStreamCreateWithFlags(&s2, cudaStreamNonBlocking);
        cudaEventCreateWithFlags(&evFork, cudaEventDisableTiming);
        cudaEventCreateWithFlags(&evQKA,  cudaEventDisableTiming);
        cudaEventCreateWithFlags(&evKBW,  cudaEventDisableTiming);
        cudaEventCreateWithFlags(&evOW,   cudaEventDisableTiming);
        cudaEventCreateWithFlags(&evF1,   cudaEventDisableTiming);
        cudaEventCreateWithFlags(&evF2,   cudaEventDisableTiming);
    }

    // fork: weight converts on s2
    cudaEventRecord(evFork, 0);
    cudaStreamWaitEvent(s2, evFork, 0);
    cvt_blk_kernel<<<2048, 256, 0, s2>>>(qw,    qwf,  H_DIM, H_DIM, H_DIM);
    cvt_blk_kernel<<<512,  256, 0, s2>>>(kva_w, kvaf, CKV_P, KVR + 64, H_DIM);
    cudaEventRecord(evQKA, s2);
    cvt_blk_kernel<<<512,  256, 0, s2>>>(kvb_w, kbwf, H_DIM, H_DIM, KVR);
    cudaEventRecord(evKBW, s2);
    cvt_blk_kernel<<<1024, 256, 0, s2>>>(ow,    owf,  H_DIM, H_DIM, NHEAD * DV);
    cudaEventRecord(evOW, s2);
    cvt_blk_kernel<<<4096, 256, 0, s2>>>(fc1w,  f1f,  NFC1, NFC1, H_DIM);
    cudaEventRecord(evF1, s2);
    cvt_fc2_blk_kernel<<<4096, 256, 0, s2>>>(fc2w, f2f);
    cudaEventRecord(evF2, s2);

    // 1. input RMSNorm
    rmsnorm_kernel<<<S_LEN, 256>>>(hidden, in_ln, sa, saf, H_DIM, H_DIM, KB_H);
    // 2+3. merged q projection (blocks 0..15) + kv_a (blocks 16..19)
    cudaStreamWaitEvent(0, evQKA, 0);
    bgemm<0><<<dim3(20, 16), 256, BG_SMEM>>>(saf, qwf, H_DIM, KB_H,
        qb, nullptr, nullptr, 0, kvaf, ckv, 16, CKV_P);
    // 4. kv RMSNorm
    rmsnorm_kernel<<<S_LEN, 256>>>(ckv, kvaln, kvn, kvnf, KVR, CKV_P, KB_KVR);
    // 5. kv_b projection
    cudaStreamWaitEvent(0, evKBW, 0);
    bgemm<0><<<dim3(16, 16), 256, BG_SMEM>>>(kvnf, kbwf, H_DIM, KB_KVR,
        kvv, nullptr, nullptr, 0, nullptr, nullptr, 0, 0);
    // 6+7. fused rope + attention operand converts
    qk_cvt_kernel<<<S_LEN, 256>>>(positions, qb, kvv, ckv, qbf, kbf);
    vt_cvt_kernel<<<dim3(S_LEN / 128, NHEAD), 256>>>(kvv, vtf);
    // 8. tensor-core attention (64-row chunks, 2 CTAs/SM)
    attn_tc<<<256, 256, AT_SMEM>>>(qbf, kbf, vtf, ctxf);
    // 9. o projection + residual
    cudaStreamWaitEvent(0, evOW, 0);
    bgemm<2><<<dim3(16, 16), 256, BG_SMEM>>>(ctxf, owf, H_DIM, KB_CTX,
        x2, hidden, nullptr, 0, nullptr, nullptr, 0, 0);
    // 10. post RMSNorm
    rmsnorm_kernel<<<S_LEN, 256>>>(x2, postln, mlp, mlpf, H_DIM, H_DIM, KB_H);
    // 11. gate softmax
    gate_kernel<<<S_LEN, 256>>>(mlp, gatew, pr);
    // 12. fc1 + SiLU*probs
    cudaStreamWaitEvent(0, evF1, 0);
    bgemm<1><<<dim3(NFC1 / 128, 16), 256, BG_SMEM>>>(mlpf, f1f, NFC1, KB_H,
        nullptr, pr, hbf, KB_FC2, nullptr, nullptr, 0, 0);
    // 13. fc2 + residual -> out
    cudaStreamWaitEvent(0, evF2, 0);
    bgemm<2><<<dim3(16, 16), 256, BG_SMEM>>>(hbf, f2f, H_DIM, KB_FC2,
        out, x2, nullptr, 0, nullptr, nullptr, 0, 0);
}

// round 16
// speedup vs baseline: 1.5601x; 1.5601x over previous
#include <cuda_runtime.h>
#include <cuda_fp16.h>
#include <math.h>
#include <stdint.h>

// ---------------------------------------------------------------- constants
#define S_LEN 2048
#define H_DIM 2048
#define NHEAD 16
#define DQK   128
#define DV    64
#define KVR   256
#define NEXP  8
#define INTER 1408
#define NFC1  (NEXP*INTER)   // 11264
#define CKV_P 512

#define KB_H    (H_DIM/64)      // 32
#define KB_KVR  (KVR/64)        // 4
#define KB_CTX  ((NHEAD*DV)/64) // 16
#define KB_FC2  (NFC1/64)       // 176

// ---------------------------------------------------------------- scratch (fp32)
__device__ float g_sa  [S_LEN*H_DIM];
__device__ float g_q   [S_LEN*H_DIM];
__device__ float g_ckv [S_LEN*CKV_P];
__device__ float g_kvn [S_LEN*KVR];
__device__ float g_kv  [S_LEN*H_DIM];
__device__ float g_x2  [S_LEN*H_DIM];
__device__ float g_mlp [S_LEN*H_DIM];
__device__ float g_pr  [S_LEN*NEXP];

// ---------------------------------------------------------------- scratch (blocked fp16)
__device__ __half g_sa_f [S_LEN*H_DIM];
__device__ __half g_kvn_f[S_LEN*KVR];
__device__ __half g_mlp_f[S_LEN*H_DIM];
__device__ __half g_ctx_f[S_LEN*NHEAD*DV];
__device__ __half g_hb_f [(size_t)S_LEN*NFC1];
__device__ __half g_qw_f [H_DIM*H_DIM];
__device__ __half g_kva_f[CKV_P*H_DIM];
__device__ __half g_kbw_f[H_DIM*KVR];
__device__ __half g_ow_f [H_DIM*NHEAD*DV];
__device__ __half g_f1_f [(size_t)NFC1*H_DIM];
__device__ __half g_f2_f [(size_t)H_DIM*NFC1];
__device__ __half g_qb_f [S_LEN*H_DIM];
__device__ __half g_kb_f [S_LEN*H_DIM];
__device__ __half g_vt_f [S_LEN*NHEAD*DV];

// ---------------------------------------------------------------- helpers
__device__ __forceinline__ uint32_t smem_u32(const void* p) {
    uint32_t a;
    asm("{ .reg .u64 t; cvta.to.shared.u64 t, %1; cvt.u32.u64 %0, t; }" : "=r"(a) : "l"(p));
    return a;
}
#define SWZ(off) ((off) ^ (((off) >> 3) & 0x70u))

__device__ __forceinline__ void ldsm_x4(uint32_t* r, uint32_t addr) {
    asm volatile("ldmatrix.sync.aligned.m8n8.x4.shared.b16 {%0,%1,%2,%3}, [%4];"
                 : "=r"(r[0]), "=r"(r[1]), "=r"(r[2]), "=r"(r[3]) : "r"(addr));
}
__device__ __forceinline__ void mma_fp16(float* c, const uint32_t* a, const uint32_t* b) {
    asm volatile("mma.sync.aligned.m16n8k16.row.col.f32.f16.f16.f32 "
                 "{%0,%1,%2,%3}, {%4,%5,%6,%7}, {%8,%9}, {%0,%1,%2,%3};"
                 : "+f"(c[0]), "+f"(c[1]), "+f"(c[2]), "+f"(c[3])
                 : "r"(a[0]), "r"(a[1]), "r"(a[2]), "r"(a[3]), "r"(b[0]), "r"(b[1]));
}
#define MBAR_INIT(a, c) asm volatile("mbarrier.init.shared.b64 [%0], %1;" :: "r"(a), "r"(c) : "memory")
#define MBAR_EXPECT(a, b) asm volatile("mbarrier.arrive.expect_tx.shared.b64 _, [%0], %1;" :: "r"(a), "r"(b) : "memory")
#define MBAR_WAIT(a, ph) do { \
    asm volatile("{\n\t.reg .pred P1;\n\tWL_%=:\n\t" \
        "mbarrier.try_wait.parity.acquire.cta.shared::cta.b64 P1, [%0], %1, 0x989680;\n\t" \
        "@P1 bra.uni WD_%=;\n\tbra.uni WL_%=;\n\tWD_%=:\n\t}" \
        :: "r"(a), "r"(ph) : "memory"); } while (0)
__device__ __forceinline__ void bulk_g2s(uint32_t dst, const void* src, uint32_t bytes, uint32_t mbar) {
    asm volatile("cp.async.bulk.shared::cluster.global.mbarrier::complete_tx::bytes [%0], [%1], %2, [%3];"
                 :: "r"(dst), "l"(src), "r"(bytes), "r"(mbar) : "memory");
}

__device__ __forceinline__ uint32_t pack2(float x, float y) {
    __half2 h = __floats2half2_rn(x, y);
    return *reinterpret_cast<uint32_t*>(&h);
}
__device__ __forceinline__ void cvt8(const float* v, uint4& p) {
    p = make_uint4(pack2(v[0], v[1]), pack2(v[2], v[3]), pack2(v[4], v[5]), pack2(v[6], v[7]));
}
__device__ __forceinline__ size_t blk_chunk_off(int blk_idx, int row, int c8) {
    uint32_t inner = (uint32_t)row * 128u + (uint32_t)c8 * 16u;
    return ((size_t)blk_idx << 14) + SWZ(inner);
}

// ---------------------------------------------------------------- weight converts
__global__ void cvt_blk_kernel(const float* __restrict__ src, __half* __restrict__ D,
                               int Npad, int Nreal, int K) {
    const int KC = K >> 3;
    const int KBk = K >> 6;
    const size_t tot = (size_t)Npad * KC;
    for (size_t idx = (size_t)blockIdx.x * blockDim.x + threadIdx.x; idx < tot;
         idx += (size_t)gridDim.x * blockDim.x) {
        int n = (int)(idx / KC), c = (int)(idx - (size_t)n * KC);
        float v[8];
        if (n < Nreal) {
            const float4 f0 = *(const float4*)(src + (size_t)n * K + c * 8);
            const float4 f1 = *(const float4*)(src + (size_t)n * K + c * 8 + 4);
            v[0]=f0.x; v[1]=f0.y; v[2]=f0.z; v[3]=f0.w; v[4]=f1.x; v[5]=f1.y; v[6]=f1.z; v[7]=f1.w;
        } else {
            #pragma unroll
            for (int j = 0; j < 8; j++) v[j] = 0.f;
        }
        uint4 p; cvt8(v, p);
        *(uint4*)((char*)D + blk_chunk_off((n >> 7) * KBk + (c >> 3), n & 127, c & 7)) = p;
    }
}

__global__ void cvt_fc2_blk_kernel(const float* __restrict__ w, __half* __restrict__ D) {
    const int KC = NFC1 >> 3;
    const size_t tot = (size_t)H_DIM * KC;
    for (size_t idx = (size_t)blockIdx.x * blockDim.x + threadIdx.x; idx < tot;
         idx += (size_t)gridDim.x * blockDim.x) {
        int n = (int)(idx / KC), c = (int)(idx - (size_t)n * KC);
        int k0 = c * 8;
        int e = k0 / INTER, i = k0 - e * INTER;
        const float* sp = w + ((size_t)e * H_DIM + n) * INTER + i;
        float v[8];
        const float4 f0 = *(const float4*)sp;
        const float4 f1 = *(const float4*)(sp + 4);
        v[0]=f0.x; v[1]=f0.y; v[2]=f0.z; v[3]=f0.w; v[4]=f1.x; v[5]=f1.y; v[6]=f1.z; v[7]=f1.w;
        uint4 p; cvt8(v, p);
        *(uint4*)((char*)D + blk_chunk_off((n >> 7) * KB_FC2 + (c >> 3), n & 127, c & 7)) = p;
    }
}

// ---------------------------------------------------------------- rmsnorm (+blocked fp16)
__global__ void rmsnorm_kernel(const float* __restrict__ x, const float* __restrict__ w,
                               float* __restrict__ y, __half* __restrict__ yf,
                               int W, int xs, int KBk)
{
    int s = blockIdx.x, tid = threadIdx.x;
    const float* xr = x + (size_t)s * xs;
    float ss = 0.f;
    for (int i = tid; i < W; i += 256) { float v = xr[i]; ss += v * v; }
    __shared__ float red[256];
    red[tid] = ss; __syncthreads();
    for (int o = 128; o > 0; o >>= 1) { if (tid < o) red[tid] += red[tid + o]; __syncthreads(); }
    float inv = rsqrtf(red[0] / (float)W + 1e-6f);
    float* yr = y + (size_t)s * W;
    const int KC = W >> 3;
    for (int c = tid; c < KC; c += 256) {
        float v[8];
        #pragma unroll
        for (int j = 0; j < 8; j++) {
            int i = c * 8 + j;
            v[j] = w[i] * xr[i] * inv;
            yr[i] = v[j];
        }
        uint4 p; cvt8(v, p);
        *(uint4*)((char*)yf + blk_chunk_off((s >> 7) * KBk + (c >> 3), s & 127, c & 7)) = p;
    }
}

// ---------------------------------------------------------------- gate softmax
__global__ void gate_kernel(const float* __restrict__ x, const float* __restrict__ w,
                            float* __restrict__ probs)
{
    int s = blockIdx.x;
    int warp = threadIdx.x >> 5, lane = threadIdx.x & 31;
    const float* xr = x + (size_t)s * H_DIM;
    const float* wr = w + (size_t)warp * H_DIM;
    float acc = 0.f;
    for (int i = lane; i < H_DIM; i += 32) acc += xr[i] * wr[i];
    #pragma unroll
    for (int o = 16; o; o >>= 1) acc += __shfl_xor_sync(0xffffffffu, acc, o);
    __shared__ float lg[8];
    if (lane == 0) lg[warp] = acc;
    __syncthreads();
    if (threadIdx.x == 0) {
        float mx = lg[0];
        #pragma unroll
        for (int e = 1; e < 8; e++) mx = fmaxf(mx, lg[e]);
        float sum = 0.f, ev[8];
        #pragma unroll
        for (int e = 0; e < 8; e++) { ev[e] = __expf(lg[e] - mx); sum += ev[e]; }
        float invs = 1.f / sum;
        #pragma unroll
        for (int e = 0; e < 8; e++) probs[(size_t)s * 8 + e] = ev[e] * invs;
    }
}

// ---------------------------------------------------------------- fused rope + attention converts
__global__ void qk_cvt_kernel(const int* __restrict__ positions,
                              const float* __restrict__ q, const float* __restrict__ kv,
                              const float* __restrict__ ckv,
                              __half* __restrict__ Qf, __half* __restrict__ Kf)
{
    const int s = blockIdx.x, tid = threadIdx.x;
    const int h = tid >> 4, d = (tid & 15) * 8;
    const float p = (float)positions[s];
    const size_t off = ((size_t)((h * 16 + (s >> 7)) * 2 + (d >> 6)) << 14)
                       + SWZ((uint32_t)(s & 127) * 128u + (uint32_t)(d & 63) * 2u);
    float cs[8], sn[8];
    if (d >= 64) {
        #pragma unroll
        for (int j = 0; j < 8; j++) {
            int jj = (d - 64 + j) & 31;
            float ang = p * exp2f(-(float)jj * 0.41524101186092f);
            __sincosf(ang, &sn[j], &cs[j]);
        }
    }
    {
        const float* qr = q + (size_t)s * H_DIM + h * DQK;
        float v[8];
        #pragma unroll
        for (int j = 0; j < 8; j++) {
            int dd = d + j;
            if (dd < 64) v[j] = qr[dd];
            else if (dd < 96) v[j] = qr[dd] * cs[j] - qr[dd + 32] * sn[j];
            else             v[j] = qr[dd] * cs[j] + qr[dd - 32] * sn[j];
        }
        uint4 pk; cvt8(v, pk);
        *(uint4*)((char*)Qf + off) = pk;
    }
    {
        const float* kr = ckv + (size_t)s * CKV_P + 256 - 64;
        const float* nr = kv + (size_t)s * H_DIM + h * DQK;
        float v[8];
        #pragma unroll
        for (int j = 0; j < 8; j++) {
            int dd = d + j;
            if (dd < 64) v[j] = nr[dd];
            else if (dd < 96) v[j] = kr[dd] * cs[j] - kr[dd + 32] * sn[j];
            else             v[j] = kr[dd] * cs[j] + kr[dd - 32] * sn[j];
        }
        uint4 pk; cvt8(v, pk);
        *(uint4*)((char*)Kf + off) = pk;
    }
}

__global__ void vt_cvt_kernel(const float* __restrict__ kv, __half* __restrict__ Vf)
{
    __shared__ float vt[128][65];
    const int sb = blockIdx.x, h = blockIdx.y, tid = threadIdx.x;
    #pragma unroll
    for (int i = 0; i < 32; i++) {
        int idx = tid + i * 256;
        int r = idx >> 6, c = idx & 63;
        vt[r][c] = kv[(size_t)(sb * 128 + r) * H_DIM + h * DQK + 64 + c];
    }
    __syncthreads();
    #pragma unroll
    for (int i = 0; i < 4; i++) {
        int idx = tid + i * 256;
        int dd = idx >> 4, s0 = (idx & 15) * 8;
        float v[8];
        #pragma unroll
        for (int j = 0; j < 8; j++) v[j] = vt[s0 + j][dd];
        uint4 p; cvt8(v, p);
        size_t off = ((size_t)(h * 16 + sb) << 14) + (size_t)(s0 >> 6) * 8192u
                     + SWZ((uint32_t)dd * 128u + (uint32_t)(s0 & 63) * 2u);
        *(uint4*)((char*)Vf + off) = p;
    }
}

// ---------------------------------------------------------------- fp16 bulk-copy GEMM
// Tile 128x128, BK=64, 3-stage pipeline, 2 CTAs/SM. Warp = 64x32.
#define BG_STAGE_B  32768u
#define BG_SMEM     (1024 + 3 * 32768)
#define OFF_A 0u
#define OFF_B 16384u

template<int EPI>
__global__ __launch_bounds__(256, 2) void bgemm(
    const __half* __restrict__ Ab, const __half* __restrict__ Bb,
    int N, int KBk,
    float* __restrict__ C, const float* __restrict__ extra,
    __half* __restrict__ Cf, int CKB,
    const __half* __restrict__ Bb2, float* __restrict__ C2, int nbSplit, int N2)
{
    extern __shared__ char smem[];
    const uint32_t sb = smem_u32(smem);
    const uint32_t tb = (sb + 1023u) & ~1023u;
    const int tid = threadIdx.x, wid = tid >> 5, lane = tid & 31;

    const __half* Buse = Bb;
    float* Cuse = C;
    int Nuse = N;
    int bx = blockIdx.x;
    if (Bb2 != nullptr && bx >= nbSplit) {
        Buse = Bb2; Cuse = C2; Nuse = N2; bx -= nbSplit;
    }
    const int n0 = bx * 128, m0 = blockIdx.y * 128;
    const int mb = blockIdx.y, nb = bx;
    const int wm = (wid >> 2) * 64;
    const int wn = (wid & 3) * 32;

    if (tid == 0) { MBAR_INIT(sb, 1); MBAR_INIT(sb + 8, 1); MBAR_INIT(sb + 16, 1); }
    __syncthreads();

    auto load_stage = [&](int t) {
        const int s = t % 3;
        const uint32_t mb_addr = sb + s * 8;
        const uint32_t st = tb + s * BG_STAGE_B;
        MBAR_EXPECT(mb_addr, BG_STAGE_B);
        bulk_g2s(st + OFF_A, (const char*)Ab   + (((size_t)mb * KBk + t) << 14), 16384u, mb_addr);
        bulk_g2s(st + OFF_B, (const char*)Buse + (((size_t)nb * KBk + t) << 14), 16384u, mb_addr);
    };

    if (tid == 0) {
        #pragma unroll
        for (int i = 0; i < 3; i++) if (i < KBk) load_stage(i);
    }

    float acc[4][4][4];
    #pragma unroll
    for (int i = 0; i < 4; i++)
        #pragma unroll
        for (int j = 0; j < 4; j++)
            #pragma unroll
            for (int k = 0; k < 4; k++) acc[i][j][k] = 0.f;

    const uint32_t a_row = lane & 15, a_chk = lane >> 4;
    const uint32_t b_row = ((lane >> 4) & 1) * 8 + (lane & 7);
    const uint32_t b_chk = (lane >> 3) & 1;

    for (int t = 0; t < KBk; t++) {
        const int s = t % 3;
        MBAR_WAIT(sb + s * 8, (t / 3) & 1);
        const uint32_t st = tb + s * BG_STAGE_B;

        #pragma unroll
        for (int ks = 0; ks < 4; ks++) {
            uint32_t a[4][4], b[4][2];
            #pragma unroll
            for (int mt = 0; mt < 4; mt++) {
                uint32_t off = SWZ((uint32_t)(wm + mt * 16 + a_row) * 128u + (ks * 2 + a_chk) * 16u);
                ldsm_x4(a[mt], st + OFF_A + off);
            }
            #pragma unroll
            for (int p = 0; p < 2; p++) {
                uint32_t off = SWZ((uint32_t)(wn + p * 16 + b_row) * 128u + (ks * 2 + b_chk) * 16u);
                uint32_t r[4];
                ldsm_x4(r, st + OFF_B + off);
                b[2*p][0]=r[0]; b[2*p][1]=r[1]; b[2*p+1][0]=r[2]; b[2*p+1][1]=r[3];
            }
            #pragma unroll
            for (int mt = 0; mt < 4; mt++)
                #pragma unroll
                for (int nt = 0; nt < 4; nt++)
                    mma_fp16(acc[mt][nt], a[mt], b[nt]);
        }
        __syncthreads();
        if (tid == 0 && t + 3 < KBk) load_stage(t + 3);
    }

    #pragma unroll
    for (int mt = 0; mt < 4; mt++) {
        #pragma unroll
        for (int half = 0; half < 2; half++) {
            const int row = m0 + wm + mt * 16 + half * 8 + (lane >> 2);
            #pragma unroll
            for (int nt = 0; nt < 4; nt++) {
                const int col = n0 + wn + nt * 8 + (lane & 3) * 2;
                float v0 = acc[mt][nt][half * 2 + 0];
                float v1 = acc[mt][nt][half * 2 + 1];
                if (EPI == 0) {
                    *(float2*)&Cuse[(size_t)row * Nuse + col] = make_float2(v0, v1);
                } else if (EPI == 2) {
                    const float2 e2 = *(const float2*)&extra[(size_t)row * Nuse + col];
                    *(float2*)&Cuse[(size_t)row * Nuse + col] = make_float2(v0 + e2.x, v1 + e2.y);
                } else {
                    float pf = extra[(size_t)row * NEXP + (col / INTER)];
                    float s0 = v0 / (1.f + __expf(-v0)) * pf;
                    float s1 = v1 / (1.f + __expf(-v1)) * pf;
                    uint32_t inner = (uint32_t)(row & 127) * 128u + (uint32_t)(col & 63) * 2u;
                    size_t off = (((size_t)(row >> 7) * CKB + (col >> 6)) << 14) + SWZ(inner);
                    *(uint32_t*)((char*)Cf + off) = pack2(s0, s1);
                }
            }
        }
    }
}

// ---------------------------------------------------------------- fp16 flash attention (1 CTA/SM, 128-row KV tiles)
#define AT_SMEM (1024 + 96 * 1024)

__global__ __launch_bounds__(256, 1) void attn_tc(
    const __half* __restrict__ Qg, const __half* __restrict__ Kg,
    const __half* __restrict__ Vg, __half* __restrict__ Cf)
{
    extern __shared__ char smem[];
    const uint32_t sbb = smem_u32(smem);
    const uint32_t tb = (sbb + 1023u) & ~1023u;
    const uint32_t QS = tb, KS = tb + 32768u, VS = tb + 65536u;

    const int tid = threadIdx.x, wid = tid >> 5, lane = tid & 31;
    const int idx = (int)gridDim.x - 1 - (int)blockIdx.x;
    const int qt = idx >> 4, h = idx & 15;
    const int wq = wid * 16;
    const int r = lane >> 2, c2 = (lane & 3) * 2;

    if (tid == 0) { MBAR_INIT(sbb, 1); MBAR_INIT(sbb + 8, 1); }
    __syncthreads();
    if (tid == 0) {
        MBAR_EXPECT(sbb, 32768u);
        bulk_g2s(QS, (const char*)Qg + ((size_t)(h * 16 + qt) << 15), 32768u, sbb);
        MBAR_EXPECT(sbb + 8, 49152u);
        bulk_g2s(KS, (const char*)Kg + ((size_t)(h * 16 + 0) << 15), 32768u, sbb + 8);
        bulk_g2s(VS, (const char*)Vg + ((size_t)(h * 16 + 0) << 14), 16384u, sbb + 8);
    }

    float sc[16][4];
    float o[8][4];
    #pragma unroll
    for (int i = 0; i < 8; i++)
        #pragma unroll
        for (int j = 0; j < 4; j++) o[i][j] = 0.f;
    float m0 = -1e30f, m1 = -1e30f, l0 = 0.f, l1 = 0.f;
    const float SCL = 0.08838834764831845f * 1.44269504088896f;

    const uint32_t a_row = lane & 15, a_chk = lane >> 4;
    const uint32_t b_row = ((lane >> 4) & 1) * 8 + (lane & 7);
    const uint32_t b_chk = (lane >> 3) & 1;

    for (int kt = 0; kt <= qt; kt++) {
        MBAR_WAIT(sbb + 8, kt & 1);
        if (kt == 0) MBAR_WAIT(sbb, 0);

        #pragma unroll
        for (int nt = 0; nt < 16; nt++)
            #pragma unroll
            for (int j = 0; j < 4; j++) sc[nt][j] = 0.f;

        #pragma unroll
        for (int kc = 0; kc < 8; kc++) {
            const uint32_t db = (kc >> 2) * 16384u;
            const uint32_t acol = ((uint32_t)(kc * 16) + a_chk * 8u) & 63u;
            uint32_t a[4];
            ldsm_x4(a, QS + db + SWZ((uint32_t)(wq + a_row) * 128u + acol * 2u));
            const uint32_t bcol = ((uint32_t)(kc * 16) + b_chk * 8u) & 63u;
            #pragma unroll
            for (int p = 0; p < 8; p++) {
                uint32_t rr[4];
                ldsm_x4(rr, KS + db + SWZ((uint32_t)(p * 16 + b_row) * 128u + bcol * 2u));
                uint32_t b0[2] = {rr[0], rr[1]}, b1[2] = {rr[2], rr[3]};
                mma_fp16(sc[2*p],   a, b0);
                mma_fp16(sc[2*p+1], a, b1);
            }
        }
        __syncthreads();
        if (tid == 0 && kt < qt) {
            const int nt1 = kt + 1;
            MBAR_EXPECT(sbb + 8, 49152u);
            bulk_g2s(KS, (const char*)Kg + ((size_t)(h * 16 + nt1) << 15), 32768u, sbb + 8);
            bulk_g2s(VS + ((uint32_t)(nt1 & 1)) * 16384u,
                     (const char*)Vg + ((size_t)(h * 16 + nt1) << 14), 16384u, sbb + 8);
        }

        const bool diag = (kt == qt);
        float nm0 = m0, nm1 = m1;
        #pragma unroll
        for (int nt = 0; nt < 16; nt++) {
            #pragma unroll
            for (int j = 0; j < 4; j++) {
                float v = sc[nt][j] * SCL;
                if (diag) {
                    int col = nt * 8 + c2 + (j & 1);
                    int rowl = wq + r + (j >> 1) * 8;
                    if (col > rowl) v = -1e30f;
                }
                sc[nt][j] = v;
            }
            nm0 = fmaxf(nm0, fmaxf(sc[nt][0], sc[nt][1]));
            nm1 = fmaxf(nm1, fmaxf(sc[nt][2], sc[nt][3]));
        }
        #pragma unroll
        for (int off = 1; off <= 2; off <<= 1) {
            nm0 = fmaxf(nm0, __shfl_xor_sync(0xffffffffu, nm0, off));
            nm1 = fmaxf(nm1, __shfl_xor_sync(0xffffffffu, nm1, off));
        }
        float rs0 = 0.f, rs1 = 0.f;
        #pragma unroll
        for (int nt = 0; nt < 16; nt++) {
            sc[nt][0] = exp2f(sc[nt][0] - nm0);
            sc[nt][1] = exp2f(sc[nt][1] - nm0);
            sc[nt][2] = exp2f(sc[nt][2] - nm1);
            sc[nt][3] = exp2f(sc[nt][3] - nm1);
            rs0 += sc[nt][0] + sc[nt][1];
            rs1 += sc[nt][2] + sc[nt][3];
        }
        #pragma unroll
        for (int off = 1; off <= 2; off <<= 1) {
            rs0 += __shfl_xor_sync(0xffffffffu, rs0, off);
            rs1 += __shfl_xor_sync(0xffffffffu, rs1, off);
        }
        float cr0 = exp2f(m0 - nm0), cr1 = exp2f(m1 - nm1);
        l0 = l0 * cr0 + rs0; l1 = l1 * cr1 + rs1;
        m0 = nm0; m1 = nm1;
        #pragma unroll
        for (int i = 0; i < 8; i++) {
            o[i][0] *= cr0; o[i][1] *= cr0;
            o[i][2] *= cr1; o[i][3] *= cr1;
        }

        const uint32_t vbase = VS + ((uint32_t)(kt & 1)) * 16384u;
        #pragma unroll
        for (int kc = 0; kc < 8; kc++) {
            uint32_t a[4];
            a[0] = pack2(sc[2*kc][0],   sc[2*kc][1]);
            a[1] = pack2(sc[2*kc][2],   sc[2*kc][3]);
            a[2] = pack2(sc[2*kc+1][0], sc[2*kc+1][1]);
            a[3] = pack2(sc[2*kc+1][2], sc[2*kc+1][3]);
            const uint32_t scol = (uint32_t)(kc * 16) + b_chk * 8u;
            const uint32_t sub = (scol >> 6) * 8192u;
            #pragma unroll
            for (int p = 0; p < 4; p++) {
                uint32_t rr[4];
                ldsm_x4(rr, vbase + sub + SWZ((uint32_t)(p * 16 + b_row) * 128u + (scol & 63u) * 2u));
                uint32_t b0[2] = {rr[0], rr[1]}, b1[2] = {rr[2], rr[3]};
                mma_fp16(o[2*p],   a, b0);
                mma_fp16(o[2*p+1], a, b1);
            }
        }
    }

    const float i0 = 1.f / l0, i1 = 1.f / l1;
    #pragma unroll
    for (int nt = 0; nt < 8; nt++) {
        const int col = h * DV + nt * 8 + c2;
        #pragma unroll
        for (int half = 0; half < 2; half++) {
            const int row = qt * 128 + wq + r + half * 8;
            float inv = half ? i1 : i0;
            float v0 = o[nt][half * 2 + 0] * inv;
            float v1 = o[nt][half * 2 + 1] * inv;
            uint32_t inner = (uint32_t)(row & 127) * 128u + (uint32_t)(col & 63) * 2u;
            size_t off = (((size_t)(row >> 7) * KB_CTX + (col >> 6)) << 14) + SWZ(inner);
            *(uint32_t*)((char*)Cf + off) = pack2(v0, v1);
        }
    }
}

// ---------------------------------------------------------------- launch
extern "C" void kernel_launch(void* const* d_in, const int* in_sizes, int n_in,
                              void* d_out, int out_size)
{
    const int*   positions = (const int*)  d_in[0];
    const float* hidden    = (const float*)d_in[1];
    const float* in_ln     = (const float*)d_in[2];
    const float* qw        = (const float*)d_in[3];
    const float* kva_w     = (const float*)d_in[4];
    const float* kvaln     = (const float*)d_in[5];
    const float* kvb_w     = (const float*)d_in[6];
    const float* ow        = (const float*)d_in[7];
    const float* postln    = (const float*)d_in[8];
    const float* gatew     = (const float*)d_in[9];
    const float* fc1w      = (const float*)d_in[10];
    const float* fc2w      = (const float*)d_in[11];
    float* out = (float*)d_out;

    float *sa, *qb, *ckv, *kvn, *kvv, *x2, *mlp, *pr;
    cudaGetSymbolAddress((void**)&sa,  g_sa);
    cudaGetSymbolAddress((void**)&qb,  g_q);
    cudaGetSymbolAddress((void**)&ckv, g_ckv);
    cudaGetSymbolAddress((void**)&kvn, g_kvn);
    cudaGetSymbolAddress((void**)&kvv, g_kv);
    cudaGetSymbolAddress((void**)&x2,  g_x2);
    cudaGetSymbolAddress((void**)&mlp, g_mlp);
    cudaGetSymbolAddress((void**)&pr,  g_pr);

    __half *saf,*kvnf,*mlpf,*ctxf,*hbf,*qwf,*kvaf,*kbwf,*owf,*f1f,*f2f,*qbf,*kbf,*vtf;
    cudaGetSymbolAddress((void**)&saf,  g_sa_f);
    cudaGetSymbolAddress((void**)&kvnf, g_kvn_f);
    cudaGetSymbolAddress((void**)&mlpf, g_mlp_f);
    cudaGetSymbolAddress((void**)&ctxf, g_ctx_f);
    cudaGetSymbolAddress((void**)&hbf,  g_hb_f);
    cudaGetSymbolAddress((void**)&qwf,  g_qw_f);
    cudaGetSymbolAddress((void**)&kvaf, g_kva_f);
    cudaGetSymbolAddress((void**)&kbwf, g_kbw_f);
    cudaGetSymbolAddress((void**)&owf,  g_ow_f);
    cudaGetSymbolAddress((void**)&f1f,  g_f1_f);
    cudaGetSymbolAddress((void**)&f2f,  g_f2_f);
    cudaGetSymbolAddress((void**)&qbf,  g_qb_f);
    cudaGetSymbolAddress((void**)&kbf,  g_kb_f);
    cudaGetSymbolAddress((void**)&vtf,  g_vt_f);

    cudaFuncSetAttribute(bgemm<0>, cudaFuncAttributeMaxDynamicSharedMemorySize, BG_SMEM);
    cudaFuncSetAttribute(bgemm<1>, cudaFuncAttributeMaxDynamicSharedMemorySize, BG_SMEM);
    cudaFuncSetAttribute(bgemm<2>, cudaFuncAttributeMaxDynamicSharedMemorySize, BG_SMEM);
    cudaFuncSetAttribute(attn_tc,  cudaFuncAttributeMaxDynamicSharedMemorySize, AT_SMEM);

    static cudaStream_t s2 = nullptr;
    static cudaEvent_t evFork = nullptr, evQKA = nullptr, evKBW = nullptr,
                       evOW = nullptr, evF1 = nullptr, evF2 = nullptr;
    if (s2 == nullptr) {
        cudaStreamCreateWithFlags(&s2, cudaStreamNonBlocking);
        cudaEventCreateWithFlags(&evFork, cudaEventDisableTiming);
        cudaEventCreateWithFlags(&evQKA,  cudaEventDisableTiming);
        cudaEventCreateWithFlags(&evKBW,  cudaEventDisableTiming);
        cudaEventCreateWithFlags(&evOW,   cudaEventDisableTiming);
        cudaEventCreateWithFlags(&evF1,   cudaEventDisableTiming);
        cudaEventCreateWithFlags(&evF2,   cudaEventDisableTiming);
    }

    // fork: weight converts on s2
    cudaEventRecord(evFork, 0);
    cudaStreamWaitEvent(s2, evFork, 0);
    cvt_blk_kernel<<<2048, 256, 0, s2>>>(qw,    qwf,  H_DIM, H_DIM, H_DIM);
    cvt_blk_kernel<<<512,  256, 0, s2>>>(kva_w, kvaf, CKV_P, KVR + 64, H_DIM);
    cudaEventRecord(evQKA, s2);
    cvt_blk_kernel<<<512,  256, 0, s2>>>(kvb_w, kbwf, H_DIM, H_DIM, KVR);
    cudaEventRecord(evKBW, s2);
    cvt_blk_kernel<<<1024, 256, 0, s2>>>(ow,    owf,  H_DIM, H_DIM, NHEAD * DV);
    cudaEventRecord(evOW, s2);
    cvt_blk_kernel<<<4096, 256, 0, s2>>>(fc1w,  f1f,  NFC1, NFC1, H_DIM);
    cudaEventRecord(evF1, s2);
    cvt_fc2_blk_kernel<<<4096, 256, 0, s2>>>(fc2w, f2f);
    cudaEventRecord(evF2, s2);

    // 1. input RMSNorm
    rmsnorm_kernel<<<S_LEN, 256>>>(hidden, in_ln, sa, saf, H_DIM, H_DIM, KB_H);
    // 2+3. merged q projection (blocks 0..15) + kv_a (blocks 16..19)
    cudaStreamWaitEvent(0, evQKA, 0);
    bgemm<0><<<dim3(20, 16), 256, BG_SMEM>>>(saf, qwf, H_DIM, KB_H,
        qb, nullptr, nullptr, 0, kvaf, ckv, 16, CKV_P);
    // 4. kv RMSNorm
    rmsnorm_kernel<<<S_LEN, 256>>>(ckv, kvaln, kvn, kvnf, KVR, CKV_P, KB_KVR);
    // 5. kv_b projection
    cudaStreamWaitEvent(0, evKBW, 0);
    bgemm<0><<<dim3(16, 16), 256, BG_SMEM>>>(kvnf, kbwf, H_DIM, KB_KVR,
        kvv, nullptr, nullptr, 0, nullptr, nullptr, 0, 0);
    // 6+7. fused rope + attention operand converts
    qk_cvt_kernel<<<S_LEN, 256>>>(positions, qb, kvv, ckv, qbf, kbf);
    vt_cvt_kernel<<<dim3(S_LEN / 128, NHEAD), 256>>>(kvv, vtf);
    // 8. tensor-core attention
    attn_tc<<<256, 256, AT_SMEM>>>(qbf, kbf, vtf, ctxf);
    // 9. o projection + residual
    cudaStreamWaitEvent(0, evOW, 0);
    bgemm<2><<<dim3(16, 16), 256, BG_SMEM>>>(ctxf, owf, H_DIM, KB_CTX,
        x2, hidden, nullptr, 0, nullptr, nullptr, 0, 0);
    // 10. post RMSNorm
    rmsnorm_kernel<<<S_LEN, 256>>>(x2, postln, mlp, mlpf, H_DIM, H_DIM, KB_H);
    // 11. gate softmax
    gate_kernel<<<S_LEN, 256>>>(mlp, gatew, pr);
    // 12. fc1 + SiLU*probs
    cudaStreamWaitEvent(0, evF1, 0);
    bgemm<1><<<dim3(NFC1 / 128, 16), 256, BG_SMEM>>>(mlpf, f1f, NFC1, KB_H,
        nullptr, pr, hbf, KB_FC2, nullptr, nullptr, 0, 0);
    // 13. fc2 + residual -> out
    cudaStreamWaitEvent(0, evF2, 0);
    bgemm<2><<<dim3(16, 16), 256, BG_SMEM>>>(hbf, f2f, H_DIM, KB_FC2,
        out, x2, nullptr, 0, nullptr, nullptr, 0, 0);
}

// round 17
// speedup vs baseline: 1.5728x; 1.0081x over previous
#include <cuda_runtime.h>
#include <cuda_fp16.h>
#include <math.h>
#include <stdint.h>

// ---------------------------------------------------------------- constants
#define S_LEN 2048
#define H_DIM 2048
#define NHEAD 16
#define DQK   128
#define DV    64
#define KVR   256
#define NEXP  8
#define INTER 1408
#define NFC1  (NEXP*INTER)   // 11264
#define CKV_P 512

#define KB_H    (H_DIM/64)      // 32
#define KB_KVR  (KVR/64)        // 4
#define KB_CTX  ((NHEAD*DV)/64) // 16
#define KB_FC2  (NFC1/64)       // 176

// ---------------------------------------------------------------- scratch (fp32)
__device__ float g_sa  [S_LEN*H_DIM];
__device__ float g_q   [S_LEN*H_DIM];
__device__ float g_ckv [S_LEN*CKV_P];
__device__ float g_kvn [S_LEN*KVR];
__device__ float g_kv  [S_LEN*H_DIM];
__device__ float g_x2  [S_LEN*H_DIM];
__device__ float g_mlp [S_LEN*H_DIM];
__device__ float g_pr  [S_LEN*NEXP];

// ---------------------------------------------------------------- scratch (blocked fp16)
__device__ __half g_sa_f [S_LEN*H_DIM];
__device__ __half g_kvn_f[S_LEN*KVR];
__device__ __half g_mlp_f[S_LEN*H_DIM];
__device__ __half g_ctx_f[S_LEN*NHEAD*DV];
__device__ __half g_hb_f [(size_t)S_LEN*NFC1];
__device__ __half g_qw_f [H_DIM*H_DIM];
__device__ __half g_kva_f[CKV_P*H_DIM];
__device__ __half g_kbw_f[H_DIM*KVR];
__device__ __half g_ow_f [H_DIM*NHEAD*DV];
__device__ __half g_f1_f [(size_t)NFC1*H_DIM];
__device__ __half g_f2_f [(size_t)H_DIM*NFC1];
__device__ __half g_qb_f [S_LEN*H_DIM];
__device__ __half g_kb_f [S_LEN*H_DIM];
__device__ __half g_vt_f [S_LEN*NHEAD*DV];

// ---------------------------------------------------------------- helpers
__device__ __forceinline__ uint32_t smem_u32(const void* p) {
    uint32_t a;
    asm("{ .reg .u64 t; cvta.to.shared.u64 t, %1; cvt.u32.u64 %0, t; }" : "=r"(a) : "l"(p));
    return a;
}
#define SWZ(off) ((off) ^ (((off) >> 3) & 0x70u))

__device__ __forceinline__ void ldsm_x4(uint32_t* r, uint32_t addr) {
    asm volatile("ldmatrix.sync.aligned.m8n8.x4.shared.b16 {%0,%1,%2,%3}, [%4];"
                 : "=r"(r[0]), "=r"(r[1]), "=r"(r[2]), "=r"(r[3]) : "r"(addr));
}
__device__ __forceinline__ void mma_fp16(float* c, const uint32_t* a, const uint32_t* b) {
    asm volatile("mma.sync.aligned.m16n8k16.row.col.f32.f16.f16.f32 "
                 "{%0,%1,%2,%3}, {%4,%5,%6,%7}, {%8,%9}, {%0,%1,%2,%3};"
                 : "+f"(c[0]), "+f"(c[1]), "+f"(c[2]), "+f"(c[3])
                 : "r"(a[0]), "r"(a[1]), "r"(a[2]), "r"(a[3]), "r"(b[0]), "r"(b[1]));
}
#define MBAR_INIT(a, c) asm volatile("mbarrier.init.shared.b64 [%0], %1;" :: "r"(a), "r"(c) : "memory")
#define MBAR_EXPECT(a, b) asm volatile("mbarrier.arrive.expect_tx.shared.b64 _, [%0], %1;" :: "r"(a), "r"(b) : "memory")
#define MBAR_WAIT(a, ph) do { \
    asm volatile("{\n\t.reg .pred P1;\n\tWL_%=:\n\t" \
        "mbarrier.try_wait.parity.acquire.cta.shared::cta.b64 P1, [%0], %1, 0x989680;\n\t" \
        "@P1 bra.uni WD_%=;\n\tbra.uni WL_%=;\n\tWD_%=:\n\t}" \
        :: "r"(a), "r"(ph) : "memory"); } while (0)
__device__ __forceinline__ void bulk_g2s(uint32_t dst, const void* src, uint32_t bytes, uint32_t mbar) {
    asm volatile("cp.async.bulk.shared::cluster.global.mbarrier::complete_tx::bytes [%0], [%1], %2, [%3];"
                 :: "r"(dst), "l"(src), "r"(bytes), "r"(mbar) : "memory");
}

__device__ __forceinline__ uint32_t pack2(float x, float y) {
    __half2 h = __floats2half2_rn(x, y);
    return *reinterpret_cast<uint32_t*>(&h);
}
__device__ __forceinline__ void cvt8(const float* v, uint4& p) {
    p = make_uint4(pack2(v[0], v[1]), pack2(v[2], v[3]), pack2(v[4], v[5]), pack2(v[6], v[7]));
}
__device__ __forceinline__ size_t blk_chunk_off(int blk_idx, int row, int c8) {
    uint32_t inner = (uint32_t)row * 128u + (uint32_t)c8 * 16u;
    return ((size_t)blk_idx << 14) + SWZ(inner);
}

// ---------------------------------------------------------------- weight converts
__global__ void cvt_blk_kernel(const float* __restrict__ src, __half* __restrict__ D,
                               int Npad, int Nreal, int K) {
    const int KC = K >> 3;
    const int KBk = K >> 6;
    const size_t tot = (size_t)Npad * KC;
    for (size_t idx = (size_t)blockIdx.x * blockDim.x + threadIdx.x; idx < tot;
         idx += (size_t)gridDim.x * blockDim.x) {
        int n = (int)(idx / KC), c = (int)(idx - (size_t)n * KC);
        float v[8];
        if (n < Nreal) {
            const float4 f0 = *(const float4*)(src + (size_t)n * K + c * 8);
            const float4 f1 = *(const float4*)(src + (size_t)n * K + c * 8 + 4);
            v[0]=f0.x; v[1]=f0.y; v[2]=f0.z; v[3]=f0.w; v[4]=f1.x; v[5]=f1.y; v[6]=f1.z; v[7]=f1.w;
        } else {
            #pragma unroll
            for (int j = 0; j < 8; j++) v[j] = 0.f;
        }
        uint4 p; cvt8(v, p);
        *(uint4*)((char*)D + blk_chunk_off((n >> 7) * KBk + (c >> 3), n & 127, c & 7)) = p;
    }
}

__global__ void cvt_fc2_blk_kernel(const float* __restrict__ w, __half* __restrict__ D) {
    const int KC = NFC1 >> 3;
    const size_t tot = (size_t)H_DIM * KC;
    for (size_t idx = (size_t)blockIdx.x * blockDim.x + threadIdx.x; idx < tot;
         idx += (size_t)gridDim.x * blockDim.x) {
        int n = (int)(idx / KC), c = (int)(idx - (size_t)n * KC);
        int k0 = c * 8;
        int e = k0 / INTER, i = k0 - e * INTER;
        const float* sp = w + ((size_t)e * H_DIM + n) * INTER + i;
        float v[8];
        const float4 f0 = *(const float4*)sp;
        const float4 f1 = *(const float4*)(sp + 4);
        v[0]=f0.x; v[1]=f0.y; v[2]=f0.z; v[3]=f0.w; v[4]=f1.x; v[5]=f1.y; v[6]=f1.z; v[7]=f1.w;
        uint4 p; cvt8(v, p);
        *(uint4*)((char*)D + blk_chunk_off((n >> 7) * KB_FC2 + (c >> 3), n & 127, c & 7)) = p;
    }
}

// ---------------------------------------------------------------- rmsnorm (+blocked fp16)
__global__ void rmsnorm_kernel(const float* __restrict__ x, const float* __restrict__ w,
                               float* __restrict__ y, __half* __restrict__ yf,
                               int W, int xs, int KBk)
{
    int s = blockIdx.x, tid = threadIdx.x;
    const float* xr = x + (size_t)s * xs;
    float ss = 0.f;
    for (int i = tid; i < W; i += 256) { float v = xr[i]; ss += v * v; }
    __shared__ float red[256];
    red[tid] = ss; __syncthreads();
    for (int o = 128; o > 0; o >>= 1) { if (tid < o) red[tid] += red[tid + o]; __syncthreads(); }
    float inv = rsqrtf(red[0] / (float)W + 1e-6f);
    float* yr = y + (size_t)s * W;
    const int KC = W >> 3;
    for (int c = tid; c < KC; c += 256) {
        float v[8];
        #pragma unroll
        for (int j = 0; j < 8; j++) {
            int i = c * 8 + j;
            v[j] = w[i] * xr[i] * inv;
            yr[i] = v[j];
        }
        uint4 p; cvt8(v, p);
        *(uint4*)((char*)yf + blk_chunk_off((s >> 7) * KBk + (c >> 3), s & 127, c & 7)) = p;
    }
}

// ---------------------------------------------------------------- gate softmax
__global__ void gate_kernel(const float* __restrict__ x, const float* __restrict__ w,
                            float* __restrict__ probs)
{
    int s = blockIdx.x;
    int warp = threadIdx.x >> 5, lane = threadIdx.x & 31;
    const float* xr = x + (size_t)s * H_DIM;
    const float* wr = w + (size_t)warp * H_DIM;
    float acc = 0.f;
    for (int i = lane; i < H_DIM; i += 32) acc += xr[i] * wr[i];
    #pragma unroll
    for (int o = 16; o; o >>= 1) acc += __shfl_xor_sync(0xffffffffu, acc, o);
    __shared__ float lg[8];
    if (lane == 0) lg[warp] = acc;
    __syncthreads();
    if (threadIdx.x == 0) {
        float mx = lg[0];
        #pragma unroll
        for (int e = 1; e < 8; e++) mx = fmaxf(mx, lg[e]);
        float sum = 0.f, ev[8];
        #pragma unroll
        for (int e = 0; e < 8; e++) { ev[e] = __expf(lg[e] - mx); sum += ev[e]; }
        float invs = 1.f / sum;
        #pragma unroll
        for (int e = 0; e < 8; e++) probs[(size_t)s * 8 + e] = ev[e] * invs;
    }
}

// ---------------------------------------------------------------- fused rope + attention converts
__global__ void qk_cvt_kernel(const int* __restrict__ positions,
                              const float* __restrict__ q, const float* __restrict__ kv,
                              const float* __restrict__ ckv,
                              __half* __restrict__ Qf, __half* __restrict__ Kf)
{
    const int s = blockIdx.x, tid = threadIdx.x;
    const int h = tid >> 4, d = (tid & 15) * 8;
    const float p = (float)positions[s];
    const size_t off = ((size_t)((h * 16 + (s >> 7)) * 2 + (d >> 6)) << 14)
                       + SWZ((uint32_t)(s & 127) * 128u + (uint32_t)(d & 63) * 2u);
    float cs[8], sn[8];
    if (d >= 64) {
        #pragma unroll
        for (int j = 0; j < 8; j++) {
            int jj = (d - 64 + j) & 31;
            float ang = p * exp2f(-(float)jj * 0.41524101186092f);
            __sincosf(ang, &sn[j], &cs[j]);
        }
    }
    {
        const float* qr = q + (size_t)s * H_DIM + h * DQK;
        float v[8];
        #pragma unroll
        for (int j = 0; j < 8; j++) {
            int dd = d + j;
            if (dd < 64) v[j] = qr[dd];
            else if (dd < 96) v[j] = qr[dd] * cs[j] - qr[dd + 32] * sn[j];
            else             v[j] = qr[dd] * cs[j] + qr[dd - 32] * sn[j];
        }
        uint4 pk; cvt8(v, pk);
        *(uint4*)((char*)Qf + off) = pk;
    }
    {
        const float* kr = ckv + (size_t)s * CKV_P + 256 - 64;
        const float* nr = kv + (size_t)s * H_DIM + h * DQK;
        float v[8];
        #pragma unroll
        for (int j = 0; j < 8; j++) {
            int dd = d + j;
            if (dd < 64) v[j] = nr[dd];
            else if (dd < 96) v[j] = kr[dd] * cs[j] - kr[dd + 32] * sn[j];
            else             v[j] = kr[dd] * cs[j] + kr[dd - 32] * sn[j];
        }
        uint4 pk; cvt8(v, pk);
        *(uint4*)((char*)Kf + off) = pk;
    }
}

__global__ void vt_cvt_kernel(const float* __restrict__ kv, __half* __restrict__ Vf)
{
    __shared__ float vt[128][65];
    const int sb = blockIdx.x, h = blockIdx.y, tid = threadIdx.x;
    #pragma unroll
    for (int i = 0; i < 32; i++) {
        int idx = tid + i * 256;
        int r = idx >> 6, c = idx & 63;
        vt[r][c] = kv[(size_t)(sb * 128 + r) * H_DIM + h * DQK + 64 + c];
    }
    __syncthreads();
    #pragma unroll
    for (int i = 0; i < 4; i++) {
        int idx = tid + i * 256;
        int dd = idx >> 4, s0 = (idx & 15) * 8;
        float v[8];
        #pragma unroll
        for (int j = 0; j < 8; j++) v[j] = vt[s0 + j][dd];
        uint4 p; cvt8(v, p);
        size_t off = ((size_t)(h * 16 + sb) << 14) + (size_t)(s0 >> 6) * 8192u
                     + SWZ((uint32_t)dd * 128u + (uint32_t)(s0 & 63) * 2u);
        *(uint4*)((char*)Vf + off) = p;
    }
}

// ---------------------------------------------------------------- fp16 bulk-copy GEMM
// Tile 128x128, BK=64, 3-stage pipeline, 2 CTAs/SM. Warp = 64x32.
#define BG_STAGE_B  32768u
#define BG_SMEM     (1024 + 3 * 32768)
#define OFF_A 0u
#define OFF_B 16384u

template<int EPI>
__global__ __launch_bounds__(256, 2) void bgemm(
    const __half* __restrict__ Ab, const __half* __restrict__ Bb,
    int N, int KBk,
    float* __restrict__ C, const float* __restrict__ extra,
    __half* __restrict__ Cf, int CKB,
    const __half* __restrict__ Bb2, float* __restrict__ C2, int nbSplit, int N2)
{
    extern __shared__ char smem[];
    const uint32_t sb = smem_u32(smem);
    const uint32_t tb = (sb + 1023u) & ~1023u;
    const int tid = threadIdx.x, wid = tid >> 5, lane = tid & 31;

    const __half* Buse = Bb;
    float* Cuse = C;
    int Nuse = N;
    int bx = blockIdx.x;
    if (Bb2 != nullptr && bx >= nbSplit) {
        Buse = Bb2; Cuse = C2; Nuse = N2; bx -= nbSplit;
    }
    const int n0 = bx * 128, m0 = blockIdx.y * 128;
    const int mb = blockIdx.y, nb = bx;
    const int wm = (wid >> 2) * 64;
    const int wn = (wid & 3) * 32;

    if (tid == 0) { MBAR_INIT(sb, 1); MBAR_INIT(sb + 8, 1); MBAR_INIT(sb + 16, 1); }
    __syncthreads();

    auto load_stage = [&](int t) {
        const int s = t % 3;
        const uint32_t mb_addr = sb + s * 8;
        const uint32_t st = tb + s * BG_STAGE_B;
        MBAR_EXPECT(mb_addr, BG_STAGE_B);
        bulk_g2s(st + OFF_A, (const char*)Ab   + (((size_t)mb * KBk + t) << 14), 16384u, mb_addr);
        bulk_g2s(st + OFF_B, (const char*)Buse + (((size_t)nb * KBk + t) << 14), 16384u, mb_addr);
    };

    if (tid == 0) {
        #pragma unroll
        for (int i = 0; i < 3; i++) if (i < KBk) load_stage(i);
    }

    float acc[4][4][4];
    #pragma unroll
    for (int i = 0; i < 4; i++)
        #pragma unroll
        for (int j = 0; j < 4; j++)
            #pragma unroll
            for (int k = 0; k < 4; k++) acc[i][j][k] = 0.f;

    const uint32_t a_row = lane & 15, a_chk = lane >> 4;
    const uint32_t b_row = ((lane >> 4) & 1) * 8 + (lane & 7);
    const uint32_t b_chk = (lane >> 3) & 1;

    for (int t = 0; t < KBk; t++) {
        const int s = t % 3;
        MBAR_WAIT(sb + s * 8, (t / 3) & 1);
        const uint32_t st = tb + s * BG_STAGE_B;

        #pragma unroll
        for (int ks = 0; ks < 4; ks++) {
            uint32_t a[4][4], b[4][2];
            #pragma unroll
            for (int mt = 0; mt < 4; mt++) {
                uint32_t off = SWZ((uint32_t)(wm + mt * 16 + a_row) * 128u + (ks * 2 + a_chk) * 16u);
                ldsm_x4(a[mt], st + OFF_A + off);
            }
            #pragma unroll
            for (int p = 0; p < 2; p++) {
                uint32_t off = SWZ((uint32_t)(wn + p * 16 + b_row) * 128u + (ks * 2 + b_chk) * 16u);
                uint32_t r[4];
                ldsm_x4(r, st + OFF_B + off);
                b[2*p][0]=r[0]; b[2*p][1]=r[1]; b[2*p+1][0]=r[2]; b[2*p+1][1]=r[3];
            }
            #pragma unroll
            for (int mt = 0; mt < 4; mt++)
                #pragma unroll
                for (int nt = 0; nt < 4; nt++)
                    mma_fp16(acc[mt][nt], a[mt], b[nt]);
        }
        __syncthreads();
        if (tid == 0 && t + 3 < KBk) load_stage(t + 3);
    }

    #pragma unroll
    for (int mt = 0; mt < 4; mt++) {
        #pragma unroll
        for (int half = 0; half < 2; half++) {
            const int row = m0 + wm + mt * 16 + half * 8 + (lane >> 2);
            #pragma unroll
            for (int nt = 0; nt < 4; nt++) {
                const int col = n0 + wn + nt * 8 + (lane & 3) * 2;
                float v0 = acc[mt][nt][half * 2 + 0];
                float v1 = acc[mt][nt][half * 2 + 1];
                if (EPI == 0) {
                    *(float2*)&Cuse[(size_t)row * Nuse + col] = make_float2(v0, v1);
                } else if (EPI == 2) {
                    const float2 e2 = *(const float2*)&extra[(size_t)row * Nuse + col];
                    *(float2*)&Cuse[(size_t)row * Nuse + col] = make_float2(v0 + e2.x, v1 + e2.y);
                } else {
                    float pf = extra[(size_t)row * NEXP + (col / INTER)];
                    float s0 = v0 / (1.f + __expf(-v0)) * pf;
                    float s1 = v1 / (1.f + __expf(-v1)) * pf;
                    uint32_t inner = (uint32_t)(row & 127) * 128u + (uint32_t)(col & 63) * 2u;
                    size_t off = (((size_t)(row >> 7) * CKB + (col >> 6)) << 14) + SWZ(inner);
                    *(uint32_t*)((char*)Cf + off) = pack2(s0, s1);
                }
            }
        }
    }
}

// ---------------------------------------------------------------- fp16 flash attention (1 CTA/SM, 128-row KV tiles)
#define AT_SMEM (1024 + 96 * 1024)

__global__ __launch_bounds__(256, 1) void attn_tc(
    const __half* __restrict__ Qg, const __half* __restrict__ Kg,
    const __half* __restrict__ Vg, __half* __restrict__ Cf)
{
    extern __shared__ char smem[];
    const uint32_t sbb = smem_u32(smem);
    const uint32_t tb = (sbb + 1023u) & ~1023u;
    const uint32_t QS = tb, KS = tb + 32768u, VS = tb + 65536u;

    const int tid = threadIdx.x, wid = tid >> 5, lane = tid & 31;
    const int idx = (int)gridDim.x - 1 - (int)blockIdx.x;
    const int qt = idx >> 4, h = idx & 15;
    const int wq = wid * 16;
    const int r = lane >> 2, c2 = (lane & 3) * 2;

    if (tid == 0) { MBAR_INIT(sbb, 1); MBAR_INIT(sbb + 8, 1); }
    __syncthreads();
    if (tid == 0) {
        MBAR_EXPECT(sbb, 32768u);
        bulk_g2s(QS, (const char*)Qg + ((size_t)(h * 16 + qt) << 15), 32768u, sbb);
        MBAR_EXPECT(sbb + 8, 49152u);
        bulk_g2s(KS, (const char*)Kg + ((size_t)(h * 16 + 0) << 15), 32768u, sbb + 8);
        bulk_g2s(VS, (const char*)Vg + ((size_t)(h * 16 + 0) << 14), 16384u, sbb + 8);
    }

    float sc[16][4];
    float o[8][4];
    #pragma unroll
    for (int i = 0; i < 8; i++)
        #pragma unroll
        for (int j = 0; j < 4; j++) o[i][j] = 0.f;
    float m0 = -1e30f, m1 = -1e30f, l0 = 0.f, l1 = 0.f;
    const float SCL = 0.08838834764831845f * 1.44269504088896f;

    const uint32_t a_row = lane & 15, a_chk = lane >> 4;
    const uint32_t b_row = ((lane >> 4) & 1) * 8 + (lane & 7);
    const uint32_t b_chk = (lane >> 3) & 1;

    for (int kt = 0; kt <= qt; kt++) {
        MBAR_WAIT(sbb + 8, kt & 1);
        if (kt == 0) MBAR_WAIT(sbb, 0);

        #pragma unroll
        for (int nt = 0; nt < 16; nt++)
            #pragma unroll
            for (int j = 0; j < 4; j++) sc[nt][j] = 0.f;

        #pragma unroll
        for (int kc = 0; kc < 8; kc++) {
            const uint32_t db = (kc >> 2) * 16384u;
            const uint32_t acol = ((uint32_t)(kc * 16) + a_chk * 8u) & 63u;
            uint32_t a[4];
            ldsm_x4(a, QS + db + SWZ((uint32_t)(wq + a_row) * 128u + acol * 2u));
            const uint32_t bcol = ((uint32_t)(kc * 16) + b_chk * 8u) & 63u;
            #pragma unroll
            for (int p = 0; p < 8; p++) {
                uint32_t rr[4];
                ldsm_x4(rr, KS + db + SWZ((uint32_t)(p * 16 + b_row) * 128u + bcol * 2u));
                uint32_t b0[2] = {rr[0], rr[1]}, b1[2] = {rr[2], rr[3]};
                mma_fp16(sc[2*p],   a, b0);
                mma_fp16(sc[2*p+1], a, b1);
            }
        }
        __syncthreads();
        if (tid == 0 && kt < qt) {
            const int nt1 = kt + 1;
            MBAR_EXPECT(sbb + 8, 49152u);
            bulk_g2s(KS, (const char*)Kg + ((size_t)(h * 16 + nt1) << 15), 32768u, sbb + 8);
            bulk_g2s(VS + ((uint32_t)(nt1 & 1)) * 16384u,
                     (const char*)Vg + ((size_t)(h * 16 + nt1) << 14), 16384u, sbb + 8);
        }

        const bool diag = (kt == qt);
        float nm0 = m0, nm1 = m1;
        #pragma unroll
        for (int nt = 0; nt < 16; nt++) {
            #pragma unroll
            for (int j = 0; j < 4; j++) {
                float v = sc[nt][j] * SCL;
                if (diag) {
                    int col = nt * 8 + c2 + (j & 1);
                    int rowl = wq + r + (j >> 1) * 8;
                    if (col > rowl) v = -1e30f;
                }
                sc[nt][j] = v;
            }
            nm0 = fmaxf(nm0, fmaxf(sc[nt][0], sc[nt][1]));
            nm1 = fmaxf(nm1, fmaxf(sc[nt][2], sc[nt][3]));
        }
        #pragma unroll
        for (int off = 1; off <= 2; off <<= 1) {
            nm0 = fmaxf(nm0, __shfl_xor_sync(0xffffffffu, nm0, off));
            nm1 = fmaxf(nm1, __shfl_xor_sync(0xffffffffu, nm1, off));
        }
        float rs0 = 0.f, rs1 = 0.f;
        #pragma unroll
        for (int nt = 0; nt < 16; nt++) {
            sc[nt][0] = exp2f(sc[nt][0] - nm0);
            sc[nt][1] = exp2f(sc[nt][1] - nm0);
            sc[nt][2] = exp2f(sc[nt][2] - nm1);
            sc[nt][3] = exp2f(sc[nt][3] - nm1);
            rs0 += sc[nt][0] + sc[nt][1];
            rs1 += sc[nt][2] + sc[nt][3];
        }
        #pragma unroll
        for (int off = 1; off <= 2; off <<= 1) {
            rs0 += __shfl_xor_sync(0xffffffffu, rs0, off);
            rs1 += __shfl_xor_sync(0xffffffffu, rs1, off);
        }
        float cr0 = exp2f(m0 - nm0), cr1 = exp2f(m1 - nm1);
        l0 = l0 * cr0 + rs0; l1 = l1 * cr1 + rs1;
        m0 = nm0; m1 = nm1;
        #pragma unroll
        for (int i = 0; i < 8; i++) {
            o[i][0] *= cr0; o[i][1] *= cr0;
            o[i][2] *= cr1; o[i][3] *= cr1;
        }

        const uint32_t vbase = VS + ((uint32_t)(kt & 1)) * 16384u;
        #pragma unroll
        for (int kc = 0; kc < 8; kc++) {
            uint32_t a[4];
            a[0] = pack2(sc[2*kc][0],   sc[2*kc][1]);
            a[1] = pack2(sc[2*kc][2],   sc[2*kc][3]);
            a[2] = pack2(sc[2*kc+1][0], sc[2*kc+1][1]);
            a[3] = pack2(sc[2*kc+1][2], sc[2*kc+1][3]);
            const uint32_t scol = (uint32_t)(kc * 16) + b_chk * 8u;
            const uint32_t sub = (scol >> 6) * 8192u;
            #pragma unroll
            for (int p = 0; p < 4; p++) {
                uint32_t rr[4];
                ldsm_x4(rr, vbase + sub + SWZ((uint32_t)(p * 16 + b_row) * 128u + (scol & 63u) * 2u));
                uint32_t b0[2] = {rr[0], rr[1]}, b1[2] = {rr[2], rr[3]};
                mma_fp16(o[2*p],   a, b0);
                mma_fp16(o[2*p+1], a, b1);
            }
        }
    }

    const float i0 = 1.f / l0, i1 = 1.f / l1;
    #pragma unroll
    for (int nt = 0; nt < 8; nt++) {
        const int col = h * DV + nt * 8 + c2;
        #pragma unroll
        for (int half = 0; half < 2; half++) {
            const int row = qt * 128 + wq + r + half * 8;
            float inv = half ? i1 : i0;
            float v0 = o[nt][half * 2 + 0] * inv;
            float v1 = o[nt][half * 2 + 1] * inv;
            uint32_t inner = (uint32_t)(row & 127) * 128u + (uint32_t)(col & 63) * 2u;
            size_t off = (((size_t)(row >> 7) * KB_CTX + (col >> 6)) << 14) + SWZ(inner);
            *(uint32_t*)((char*)Cf + off) = pack2(v0, v1);
        }
    }
}

// ---------------------------------------------------------------- launch
extern "C" void kernel_launch(void* const* d_in, const int* in_sizes, int n_in,
                              void* d_out, int out_size)
{
    const int*   positions = (const int*)  d_in[0];
    const float* hidden    = (const float*)d_in[1];
    const float* in_ln     = (const float*)d_in[2];
    const float* qw        = (const float*)d_in[3];
    const float* kva_w     = (const float*)d_in[4];
    const float* kvaln     = (const float*)d_in[5];
    const float* kvb_w     = (const float*)d_in[6];
    const float* ow        = (const float*)d_in[7];
    const float* postln    = (const float*)d_in[8];
    const float* gatew     = (const float*)d_in[9];
    const float* fc1w      = (const float*)d_in[10];
    const float* fc2w      = (const float*)d_in[11];
    float* out = (float*)d_out;

    float *sa, *qb, *ckv, *kvn, *kvv, *x2, *mlp, *pr;
    cudaGetSymbolAddress((void**)&sa,  g_sa);
    cudaGetSymbolAddress((void**)&qb,  g_q);
    cudaGetSymbolAddress((void**)&ckv, g_ckv);
    cudaGetSymbolAddress((void**)&kvn, g_kvn);
    cudaGetSymbolAddress((void**)&kvv, g_kv);
    cudaGetSymbolAddress((void**)&x2,  g_x2);
    cudaGetSymbolAddress((void**)&mlp, g_mlp);
    cudaGetSymbolAddress((void**)&pr,  g_pr);

    __half *saf,*kvnf,*mlpf,*ctxf,*hbf,*qwf,*kvaf,*kbwf,*owf,*f1f,*f2f,*qbf,*kbf,*vtf;
    cudaGetSymbolAddress((void**)&saf,  g_sa_f);
    cudaGetSymbolAddress((void**)&kvnf, g_kvn_f);
    cudaGetSymbolAddress((void**)&mlpf, g_mlp_f);
    cudaGetSymbolAddress((void**)&ctxf, g_ctx_f);
    cudaGetSymbolAddress((void**)&hbf,  g_hb_f);
    cudaGetSymbolAddress((void**)&qwf,  g_qw_f);
    cudaGetSymbolAddress((void**)&kvaf, g_kva_f);
    cudaGetSymbolAddress((void**)&kbwf, g_kbw_f);
    cudaGetSymbolAddress((void**)&owf,  g_ow_f);
    cudaGetSymbolAddress((void**)&f1f,  g_f1_f);
    cudaGetSymbolAddress((void**)&f2f,  g_f2_f);
    cudaGetSymbolAddress((void**)&qbf,  g_qb_f);
    cudaGetSymbolAddress((void**)&kbf,  g_kb_f);
    cudaGetSymbolAddress((void**)&vtf,  g_vt_f);

    cudaFuncSetAttribute(bgemm<0>, cudaFuncAttributeMaxDynamicSharedMemorySize, BG_SMEM);
    cudaFuncSetAttribute(bgemm<1>, cudaFuncAttributeMaxDynamicSharedMemorySize, BG_SMEM);
    cudaFuncSetAttribute(bgemm<2>, cudaFuncAttributeMaxDynamicSharedMemorySize, BG_SMEM);
    cudaFuncSetAttribute(attn_tc,  cudaFuncAttributeMaxDynamicSharedMemorySize, AT_SMEM);

    static cudaStream_t s2 = nullptr;
    static cudaEvent_t evFork = nullptr, evKVA = nullptr, evKBW = nullptr,
                       evOW = nullptr, evF1 = nullptr, evF2 = nullptr,
                       evSA = nullptr, evQP = nullptr;
    if (s2 == nullptr) {
        cudaStreamCreateWithFlags(&s2, cudaStreamNonBlocking);
        cudaEventCreateWithFlags(&evFork, cudaEventDisableTiming);
        cudaEventCreateWithFlags(&evKVA,  cudaEventDisableTiming);
        cudaEventCreateWithFlags(&evKBW,  cudaEventDisableTiming);
        cudaEventCreateWithFlags(&evOW,   cudaEventDisableTiming);
        cudaEventCreateWithFlags(&evF1,   cudaEventDisableTiming);
        cudaEventCreateWithFlags(&evF2,   cudaEventDisableTiming);
        cudaEventCreateWithFlags(&evSA,   cudaEventDisableTiming);
        cudaEventCreateWithFlags(&evQP,   cudaEventDisableTiming);
    }

    // fork: converts (+ q projection) on s2
    cudaEventRecord(evFork, 0);
    cudaStreamWaitEvent(s2, evFork, 0);
    cvt_blk_kernel<<<512,  256, 0, s2>>>(kva_w, kvaf, CKV_P, KVR + 64, H_DIM);
    cudaEventRecord(evKVA, s2);
    cvt_blk_kernel<<<512,  256, 0, s2>>>(kvb_w, kbwf, H_DIM, H_DIM, KVR);
    cudaEventRecord(evKBW, s2);
    cvt_blk_kernel<<<2048, 256, 0, s2>>>(qw,    qwf,  H_DIM, H_DIM, H_DIM);

    // 1. input RMSNorm (main, overlaps converts)
    rmsnorm_kernel<<<S_LEN, 256>>>(hidden, in_ln, sa, saf, H_DIM, H_DIM, KB_H);
    cudaEventRecord(evSA, 0);

    // 2. q projection on s2 (after qw convert in-order; needs saf)
    cudaStreamWaitEvent(s2, evSA, 0);
    bgemm<0><<<dim3(16, 16), 256, BG_SMEM, s2>>>(saf, qwf, H_DIM, KB_H,
        qb, nullptr, nullptr, 0, nullptr, nullptr, 0, 0);
    cudaEventRecord(evQP, s2);
    // remaining converts on s2 (after q-proj)
    cvt_blk_kernel<<<1024, 256, 0, s2>>>(ow,   owf, H_DIM, H_DIM, NHEAD * DV);
    cudaEventRecord(evOW, s2);
    cvt_blk_kernel<<<4096, 256, 0, s2>>>(fc1w, f1f, NFC1, NFC1, H_DIM);
    cudaEventRecord(evF1, s2);
    cvt_fc2_blk_kernel<<<4096, 256, 0, s2>>>(fc2w, f2f);
    cudaEventRecord(evF2, s2);

    // 3. kv_a projection (main, concurrent with q-proj)
    cudaStreamWaitEvent(0, evKVA, 0);
    bgemm<0><<<dim3(4, 16), 256, BG_SMEM>>>(saf, kvaf, CKV_P, KB_H,
        ckv, nullptr, nullptr, 0, nullptr, nullptr, 0, 0);
    // 4. kv RMSNorm
    rmsnorm_kernel<<<S_LEN, 256>>>(ckv, kvaln, kvn, kvnf, KVR, CKV_P, KB_KVR);
    // 5. kv_b projection
    cudaStreamWaitEvent(0, evKBW, 0);
    bgemm<0><<<dim3(16, 16), 256, BG_SMEM>>>(kvnf, kbwf, H_DIM, KB_KVR,
        kvv, nullptr, nullptr, 0, nullptr, nullptr, 0, 0);
    // 6. V transpose convert (only needs kvv)
    vt_cvt_kernel<<<dim3(S_LEN / 128, NHEAD), 256>>>(kvv, vtf);
    // 7. fused rope + qk convert (needs qb from s2)
    cudaStreamWaitEvent(0, evQP, 0);
    qk_cvt_kernel<<<S_LEN, 256>>>(positions, qb, kvv, ckv, qbf, kbf);
    // 8. tensor-core attention
    attn_tc<<<256, 256, AT_SMEM>>>(qbf, kbf, vtf, ctxf);
    // 9. o projection + residual
    cudaStreamWaitEvent(0, evOW, 0);
    bgemm<2><<<dim3(16, 16), 256, BG_SMEM>>>(ctxf, owf, H_DIM, KB_CTX,
        x2, hidden, nullptr, 0, nullptr, nullptr, 0, 0);
    // 10. post RMSNorm
    rmsnorm_kernel<<<S_LEN, 256>>>(x2, postln, mlp, mlpf, H_DIM, H_DIM, KB_H);
    // 11. gate softmax
    gate_kernel<<<S_LEN, 256>>>(mlp, gatew, pr);
    // 12. fc1 + SiLU*probs
    cudaStreamWaitEvent(0, evF1, 0);
    bgemm<1><<<dim3(NFC1 / 128, 16), 256, BG_SMEM>>>(mlpf, f1f, NFC1, KB_H,
        nullptr, pr, hbf, KB_FC2, nullptr, nullptr, 0, 0);
    // 13. fc2 + residual -> out
    cudaStreamWaitEvent(0, evF2, 0);
    bgemm<2><<<dim3(16, 16), 256, BG_SMEM>>>(hbf, f2f, H_DIM, KB_FC2,
        out, x2, nullptr, 0, nullptr, nullptr, 0, 0);
}